// round 13
// baseline (speedup 1.0000x reference)
#include <cuda_runtime.h>
#include <cuda_bf16.h>
#include <cuda_fp16.h>
#include <cstdint>
#include <math.h>

#define NMAX 50000
#define EFIX 800000
#define FIN  128
#define HC   256   // heads(8) * Hd(32)
#define H1   8
#define C2   32
#define FOUT 16
#define NBLK ((NMAX + 255) / 256)

// ---------------- scratch (static device globals; no allocation) -------------
__device__ float g_h1   [NMAX * HC];
__device__ __half2 g_h1h[NMAX * (HC / 2)];   // fp16 mirror for agg1 gather
__device__ float g_h1a  [NMAX * HC];
__device__ float g_asrc1[NMAX * H1];
__device__ float g_adst1[NMAX * H1];
__device__ float g_h2   [NMAX * C2];
__device__ float g_asrc2[NMAX];
__device__ float g_adst2[NMAX];
__device__ int   g_deg  [NMAX];
__device__ int   g_cur  [NMAX];
__device__ int   g_off  [NMAX + 1];
__device__ int   g_csr  [EFIX];
__device__ int   g_bsum [256];
__device__ int   g_bpre [256];
__device__ int   g_is64;

__device__ __forceinline__ float leaky(float x) { return x > 0.f ? x : 0.2f * x; }
__device__ __forceinline__ float elu(float x)   { return x > 0.f ? x : expm1f(x); }

// ---------------- tensor-core helpers ----------------------------------------
__device__ __forceinline__ unsigned smem_u32(const void* p) {
    unsigned addr;
    asm("{ .reg .u64 t; cvta.to.shared.u64 t, %1; cvt.u32.u64 %0, t; }"
        : "=r"(addr) : "l"(p));
    return addr;
}
__device__ __forceinline__ void ldsm_x4(unsigned& r0, unsigned& r1, unsigned& r2,
                                        unsigned& r3, unsigned addr) {
    asm volatile("ldmatrix.sync.aligned.m8n8.x4.shared.b16 {%0,%1,%2,%3}, [%4];"
                 : "=r"(r0), "=r"(r1), "=r"(r2), "=r"(r3) : "r"(addr));
}
__device__ __forceinline__ void ldsm_x4t(unsigned& r0, unsigned& r1, unsigned& r2,
                                         unsigned& r3, unsigned addr) {
    asm volatile("ldmatrix.sync.aligned.m8n8.x4.trans.shared.b16 {%0,%1,%2,%3}, [%4];"
                 : "=r"(r0), "=r"(r1), "=r"(r2), "=r"(r3) : "r"(addr));
}
__device__ __forceinline__ void mma_bf16(float* d, const unsigned* a,
                                         unsigned b0, unsigned b1) {
    asm volatile(
        "mma.sync.aligned.m16n8k16.row.col.f32.bf16.bf16.f32 "
        "{%0,%1,%2,%3}, {%4,%5,%6,%7}, {%8,%9}, {%0,%1,%2,%3};"
        : "+f"(d[0]), "+f"(d[1]), "+f"(d[2]), "+f"(d[3])
        : "r"(a[0]), "r"(a[1]), "r"(a[2]), "r"(a[3]), "r"(b0), "r"(b1));
}

// ---------------- dtype detection -------------------------------------------
__global__ void k_detect(const int* __restrict__ ei) {
    int z = 1;
    for (int i = 0; i < 64; i++)
        if (ei[2 * i + 1] != 0) { z = 0; break; }
    g_is64 = z;
}

// ---------------- CSR build --------------------------------------------------
__global__ void k_zero(int n) {
    int i = blockIdx.x * blockDim.x + threadIdx.x;
    if (i < n) { g_deg[i] = 0; g_cur[i] = 0; }
}

__global__ void k_count(const int* __restrict__ ei, int e, int n) {
    int i = blockIdx.x * blockDim.x + threadIdx.x;
    if (i < e) {
        int dst = g_is64 ? ei[2 * (e + i)] : ei[e + i];
        if ((unsigned)dst < (unsigned)n) atomicAdd(&g_deg[dst], 1);
    }
}

__global__ __launch_bounds__(256) void k_scanA(int n) {
    __shared__ int ws[8];
    int tid = threadIdx.x, lane = tid & 31, wid = tid >> 5;
    int idx = blockIdx.x * 256 + tid;
    int v = (idx < n) ? g_deg[idx] : 0;
    #pragma unroll
    for (int o = 16; o > 0; o >>= 1) v += __shfl_xor_sync(0xffffffffu, v, o);
    if (lane == 0) ws[wid] = v;
    __syncthreads();
    if (tid == 0) {
        int s = 0;
        #pragma unroll
        for (int i = 0; i < 8; i++) s += ws[i];
        g_bsum[blockIdx.x] = s;
    }
}

__global__ __launch_bounds__(256) void k_scanB(int nblk, int n) {
    __shared__ int wpre[8];
    int tid = threadIdx.x, lane = tid & 31, wid = tid >> 5;
    int v = (tid < nblk) ? g_bsum[tid] : 0;
    int inc = v;
    #pragma unroll
    for (int o = 1; o < 32; o <<= 1) {
        int t = __shfl_up_sync(0xffffffffu, inc, o);
        if (lane >= o) inc += t;
    }
    if (lane == 31) wpre[wid] = inc;
    __syncthreads();
    if (tid == 0) {
        int run = 0;
        #pragma unroll
        for (int i = 0; i < 8; i++) { int t = wpre[i]; wpre[i] = run; run += t; }
    }
    __syncthreads();
    int pre = inc - v + wpre[wid];
    if (tid < nblk) g_bpre[tid] = pre;
    if (tid == nblk - 1) g_off[n] = pre + v;
}

__global__ __launch_bounds__(256) void k_scanC(int n) {
    __shared__ int wpre[8];
    int tid = threadIdx.x, lane = tid & 31, wid = tid >> 5;
    int idx = blockIdx.x * 256 + tid;
    int v = (idx < n) ? g_deg[idx] : 0;
    int inc = v;
    #pragma unroll
    for (int o = 1; o < 32; o <<= 1) {
        int t = __shfl_up_sync(0xffffffffu, inc, o);
        if (lane >= o) inc += t;
    }
    if (lane == 31) wpre[wid] = inc;
    __syncthreads();
    if (tid == 0) {
        int run = 0;
        #pragma unroll
        for (int i = 0; i < 8; i++) { int t = wpre[i]; wpre[i] = run; run += t; }
    }
    __syncthreads();
    if (idx < n) g_off[idx] = g_bpre[blockIdx.x] + wpre[wid] + inc - v;
}

__global__ void k_scatter(const int* __restrict__ ei, int e, int n) {
    int i = blockIdx.x * blockDim.x + threadIdx.x;
    if (i < e) {
        int src, dst;
        if (g_is64) { src = ei[2 * i]; dst = ei[2 * (e + i)]; }
        else        { src = ei[i];     dst = ei[e + i]; }
        if ((unsigned)dst < (unsigned)n && (unsigned)src < (unsigned)n) {
            int pos = atomicAdd(&g_cur[dst], 1);
            g_csr[g_off[dst] + pos] = src;
        }
    }
}

// ---------------- GEMM1 (tensor cores): h1 = x @ W1 --------------------------
// bf16 m16n8k16 mma with 2-term split (hi+lo): acc = xh*wh + xh*wl + xl*wh.
// Epilogue writes fp32 h1 AND a packed-fp16 mirror (g_h1h) for agg1's gather.
#define XPAD 40
#define WPAD 136
__global__ __launch_bounds__(256) void k_gemm1(const float* __restrict__ x,
                                               const float* __restrict__ W, int n) {
    __shared__ __nv_bfloat16 xh[128][XPAD];
    __shared__ __nv_bfloat16 xl[128][XPAD];
    __shared__ __nv_bfloat16 wh[32][WPAD];
    __shared__ __nv_bfloat16 wl[32][WPAD];

    int row0 = blockIdx.x * 128;
    int col0 = blockIdx.y * 128;
    int t = threadIdx.x;
    int lane = t & 31, warp = t >> 5;
    int wr = (warp & 3) * 32;
    int wc = (warp >> 2) * 64;

    float acc[2][8][4];
    #pragma unroll
    for (int i = 0; i < 2; i++)
        #pragma unroll
        for (int j = 0; j < 8; j++)
            #pragma unroll
            for (int q = 0; q < 4; q++) acc[i][j][q] = 0.f;

    int grp = lane >> 3;
    int rIn = (lane & 7) + ((grp & 1) << 3);
    int cIn = (grp >> 1) << 3;

    for (int kc = 0; kc < FIN; kc += 32) {
        #pragma unroll
        for (int i = 0; i < 4; i++) {
            int f = t + i * 256;
            int r = f >> 3, kq = f & 7;
            int gr = row0 + r;
            float4 v = make_float4(0.f, 0.f, 0.f, 0.f);
            if (gr < n) v = *(const float4*)&x[(size_t)gr * FIN + kc + kq * 4];
            float vv[4] = {v.x, v.y, v.z, v.w};
            #pragma unroll
            for (int j = 0; j < 4; j++) {
                __nv_bfloat16 hi = __float2bfloat16(vv[j]);
                xh[r][kq * 4 + j] = hi;
                xl[r][kq * 4 + j] = __float2bfloat16(vv[j] - __bfloat162float(hi));
            }
        }
        #pragma unroll
        for (int i = 0; i < 4; i++) {
            int f = t + i * 256;
            int k = f >> 5, c4 = f & 31;
            float4 v = *(const float4*)&W[(size_t)(kc + k) * HC + col0 + c4 * 4];
            float vv[4] = {v.x, v.y, v.z, v.w};
            #pragma unroll
            for (int j = 0; j < 4; j++) {
                __nv_bfloat16 hi = __float2bfloat16(vv[j]);
                wh[k][c4 * 4 + j] = hi;
                wl[k][c4 * 4 + j] = __float2bfloat16(vv[j] - __bfloat162float(hi));
            }
        }
        __syncthreads();

        #pragma unroll
        for (int k16 = 0; k16 < 32; k16 += 16) {
            unsigned Ah[2][4], Al[2][4];
            #pragma unroll
            for (int tt = 0; tt < 2; tt++) {
                int row = wr + tt * 16 + rIn;
                int col = k16 + cIn;
                ldsm_x4(Ah[tt][0], Ah[tt][1], Ah[tt][2], Ah[tt][3],
                        smem_u32(&xh[row][col]));
                ldsm_x4(Al[tt][0], Al[tt][1], Al[tt][2], Al[tt][3],
                        smem_u32(&xl[row][col]));
            }
            #pragma unroll
            for (int p = 0; p < 4; p++) {
                int row = k16 + rIn;
                int col = wc + p * 16 + cIn;
                unsigned Bh[4], Bl[4];
                ldsm_x4t(Bh[0], Bh[1], Bh[2], Bh[3], smem_u32(&wh[row][col]));
                ldsm_x4t(Bl[0], Bl[1], Bl[2], Bl[3], smem_u32(&wl[row][col]));
                #pragma unroll
                for (int tt = 0; tt < 2; tt++) {
                    #pragma unroll
                    for (int q = 0; q < 2; q++) {
                        float* d = acc[tt][p * 2 + q];
                        mma_bf16(d, Ah[tt], Bh[2 * q], Bh[2 * q + 1]);
                        mma_bf16(d, Ah[tt], Bl[2 * q], Bl[2 * q + 1]);
                        mma_bf16(d, Al[tt], Bh[2 * q], Bh[2 * q + 1]);
                    }
                }
            }
        }
        __syncthreads();
    }

    #pragma unroll
    for (int tt = 0; tt < 2; tt++) {
        #pragma unroll
        for (int j = 0; j < 8; j++) {
            int gr = row0 + wr + tt * 16 + (lane >> 2);
            int gc = col0 + wc + j * 8 + (lane & 3) * 2;
            if (gr < n) {
                *(float2*)&g_h1[(size_t)gr * HC + gc] =
                    make_float2(acc[tt][j][0], acc[tt][j][1]);
                g_h1h[(size_t)gr * (HC / 2) + (gc >> 1)] =
                    __floats2half2_rn(acc[tt][j][0], acc[tt][j][1]);
            }
            if (gr + 8 < n) {
                *(float2*)&g_h1[(size_t)(gr + 8) * HC + gc] =
                    make_float2(acc[tt][j][2], acc[tt][j][3]);
                g_h1h[(size_t)(gr + 8) * (HC / 2) + (gc >> 1)] =
                    __floats2half2_rn(acc[tt][j][2], acc[tt][j][3]);
            }
        }
    }
}

// ---------------- attention scores layer 1 (warp per node) -------------------
__global__ __launch_bounds__(256) void k_attn1(const float* __restrict__ as,
                                               const float* __restrict__ adv, int n) {
    __shared__ float s_s[HC], s_d[HC];
    if (threadIdx.x < HC) { s_s[threadIdx.x] = as[threadIdx.x]; s_d[threadIdx.x] = adv[threadIdx.x]; }
    __syncthreads();
    int w = (blockIdx.x * blockDim.x + threadIdx.x) >> 5;
    int lane = threadIdx.x & 31;
    if (w >= n) return;
    float4 v0 = *(const float4*)&g_h1[(size_t)w * HC + lane * 8];
    float4 v1 = *(const float4*)&g_h1[(size_t)w * HC + lane * 8 + 4];
    const float* ss = &s_s[lane * 8];
    const float* sd = &s_d[lane * 8];
    float ps = v0.x*ss[0] + v0.y*ss[1] + v0.z*ss[2] + v0.w*ss[3]
             + v1.x*ss[4] + v1.y*ss[5] + v1.z*ss[6] + v1.w*ss[7];
    float pd = v0.x*sd[0] + v0.y*sd[1] + v0.z*sd[2] + v0.w*sd[3]
             + v1.x*sd[4] + v1.y*sd[5] + v1.z*sd[6] + v1.w*sd[7];
    ps += __shfl_xor_sync(0xffffffffu, ps, 1);
    pd += __shfl_xor_sync(0xffffffffu, pd, 1);
    ps += __shfl_xor_sync(0xffffffffu, ps, 2);
    pd += __shfl_xor_sync(0xffffffffu, pd, 2);
    if ((lane & 3) == 0) {
        g_asrc1[w * H1 + (lane >> 2)] = ps;
        g_adst1[w * H1 + (lane >> 2)] = pd;
    }
}

// ---------------- layer-1 aggregation + ELU (single pass, fp16 gather) -------
__global__ __launch_bounds__(256) void k_agg1(const float* __restrict__ b1, int n) {
    int w = (blockIdx.x * blockDim.x + threadIdx.x) >> 5;
    int lane = threadIdx.x & 31;
    if (w >= n) return;
    int beg = g_off[w], end = g_off[w + 1];

    int h1i = lane >> 3;
    int h2i = 4 + h1i;
    float adh1 = g_adst1[w * H1 + h1i];
    float adh2 = g_adst1[w * H1 + h2i];

    float ssum1 = 0.f, ssum2 = 0.f;
    float4 acc1 = make_float4(0.f, 0.f, 0.f, 0.f);
    float4 acc2 = make_float4(0.f, 0.f, 0.f, 0.f);

    for (int base = beg; base < end; base += 32) {
        int cnt = end - base; if (cnt > 32) cnt = 32;
        int my = (lane < cnt) ? g_csr[base + lane] : 0;
        for (int t = 0; t < cnt; t++) {
            int src = __shfl_sync(0xffffffffu, my, t);
            float ev1 = __expf(leaky(g_asrc1[src * H1 + h1i] + adh1));
            float ev2 = __expf(leaky(g_asrc1[src * H1 + h2i] + adh2));
            ssum1 += ev1; ssum2 += ev2;
            // fp16 gather: channels [lane*4, +4) and [128+lane*4, +4)
            uint2 q1 = *(const uint2*)(g_h1h + (size_t)src * (HC / 2) + lane * 2);
            uint2 q2 = *(const uint2*)(g_h1h + (size_t)src * (HC / 2) + 64 + lane * 2);
            float2 a = __half22float2(*(__half2*)&q1.x);
            float2 b = __half22float2(*(__half2*)&q1.y);
            float2 c = __half22float2(*(__half2*)&q2.x);
            float2 d = __half22float2(*(__half2*)&q2.y);
            acc1.x += ev1 * a.x; acc1.y += ev1 * a.y; acc1.z += ev1 * b.x; acc1.w += ev1 * b.y;
            acc2.x += ev2 * c.x; acc2.y += ev2 * c.y; acc2.z += ev2 * d.x; acc2.w += ev2 * d.y;
        }
    }
    {
        float es1 = __expf(leaky(g_asrc1[w * H1 + h1i] + adh1));
        float es2 = __expf(leaky(g_asrc1[w * H1 + h2i] + adh2));
        ssum1 += es1; ssum2 += es2;
        uint2 q1 = *(const uint2*)(g_h1h + (size_t)w * (HC / 2) + lane * 2);
        uint2 q2 = *(const uint2*)(g_h1h + (size_t)w * (HC / 2) + 64 + lane * 2);
        float2 a = __half22float2(*(__half2*)&q1.x);
        float2 b = __half22float2(*(__half2*)&q1.y);
        float2 c = __half22float2(*(__half2*)&q2.x);
        float2 d = __half22float2(*(__half2*)&q2.y);
        acc1.x += es1 * a.x; acc1.y += es1 * a.y; acc1.z += es1 * b.x; acc1.w += es1 * b.y;
        acc2.x += es2 * c.x; acc2.y += es2 * c.y; acc2.z += es2 * d.x; acc2.w += es2 * d.y;
    }
    float iv1 = 1.f / (ssum1 + 1e-16f);
    float iv2 = 1.f / (ssum2 + 1e-16f);
    float4 bb1 = *(const float4*)&b1[lane * 4];
    float4 bb2 = *(const float4*)&b1[128 + lane * 4];
    acc1.x = elu(acc1.x * iv1 + bb1.x); acc1.y = elu(acc1.y * iv1 + bb1.y);
    acc1.z = elu(acc1.z * iv1 + bb1.z); acc1.w = elu(acc1.w * iv1 + bb1.w);
    acc2.x = elu(acc2.x * iv2 + bb2.x); acc2.y = elu(acc2.y * iv2 + bb2.y);
    acc2.z = elu(acc2.z * iv2 + bb2.z); acc2.w = elu(acc2.w * iv2 + bb2.w);
    *(float4*)&g_h1a[(size_t)w * HC + lane * 4]       = acc1;
    *(float4*)&g_h1a[(size_t)w * HC + 128 + lane * 4] = acc2;
}

// ---------------- GEMM2 (+ fused attn2): h2 = h1a @ W2 -----------------------
__global__ __launch_bounds__(256) void k_gemm2(const float* __restrict__ W2,
                                               const float* __restrict__ att_s2,
                                               const float* __restrict__ att_d2, int n) {
    __shared__ float w2s[256 * 32];
    __shared__ float hs[16 * 256];
    __shared__ float a2s[32], a2d[32];
    int t = threadIdx.x;
    if (t < 32) { a2s[t] = att_s2[t]; a2d[t] = att_d2[t]; }
    #pragma unroll
    for (int i = 0; i < 8; i++)
        ((float4*)w2s)[t + i * 256] = ((const float4*)W2)[t + i * 256];
    int row0 = blockIdx.x * 16;
    #pragma unroll
    for (int i = 0; i < 4; i++) {
        int f = t + i * 256;
        int r = f >> 6, c4 = f & 63;
        int gr = row0 + r;
        float4 v = make_float4(0.f, 0.f, 0.f, 0.f);
        if (gr < n) v = ((const float4*)&g_h1a[(size_t)gr * HC])[c4];
        ((float4*)hs)[f] = v;
    }
    __syncthreads();
    int col = t & 31, rg = t >> 5;
    float acc0 = 0.f, acc1 = 0.f;
    for (int k = 0; k < 256; k += 4) {
        float b0 = w2s[k * 32 + col];
        float b1 = w2s[(k + 1) * 32 + col];
        float b2 = w2s[(k + 2) * 32 + col];
        float b3 = w2s[(k + 3) * 32 + col];
        float4 a0 = *(float4*)&hs[rg * 256 + k];
        float4 a1 = *(float4*)&hs[(rg + 8) * 256 + k];
        acc0 += a0.x * b0 + a0.y * b1 + a0.z * b2 + a0.w * b3;
        acc1 += a1.x * b0 + a1.y * b1 + a1.z * b2 + a1.w * b3;
    }
    int gr0 = row0 + rg, gr1 = row0 + rg + 8;
    if (gr0 < n) g_h2[(size_t)gr0 * 32 + col] = acc0;
    if (gr1 < n) g_h2[(size_t)gr1 * 32 + col] = acc1;
    float s0 = acc0 * a2s[col], d0 = acc0 * a2d[col];
    float s1 = acc1 * a2s[col], d1 = acc1 * a2d[col];
    #pragma unroll
    for (int o = 16; o > 0; o >>= 1) {
        s0 += __shfl_xor_sync(0xffffffffu, s0, o);
        d0 += __shfl_xor_sync(0xffffffffu, d0, o);
        s1 += __shfl_xor_sync(0xffffffffu, s1, o);
        d1 += __shfl_xor_sync(0xffffffffu, d1, o);
    }
    if (col == 0) {
        if (gr0 < n) { g_asrc2[gr0] = s0; g_adst2[gr0] = d0; }
        if (gr1 < n) { g_asrc2[gr1] = s1; g_adst2[gr1] = d1; }
    }
}

// ---------------- layer-2 agg (single pass) + ELU + (@Wout + bout) -----------
__global__ __launch_bounds__(256) void k_agg2(const float* __restrict__ b2,
                                              const float* __restrict__ Wout,
                                              const float* __restrict__ bout,
                                              float* __restrict__ out, int n) {
    __shared__ float wos[32 * 16];
    __shared__ float bos[16];
    __shared__ float vsh[8][32];
    wos[threadIdx.x]       = Wout[threadIdx.x];
    wos[threadIdx.x + 256] = Wout[threadIdx.x + 256];
    if (threadIdx.x < 16)  bos[threadIdx.x] = bout[threadIdx.x];
    __syncthreads();

    int w = (blockIdx.x * blockDim.x + threadIdx.x) >> 5;
    int lane = threadIdx.x & 31;
    int wl = threadIdx.x >> 5;
    if (w >= n) return;

    float adv = g_adst2[w];
    int beg = g_off[w], end = g_off[w + 1];

    float ssum = 0.f, acc = 0.f;
    for (int base = beg; base < end; base += 32) {
        int cnt = end - base; if (cnt > 32) cnt = 32;
        int my = (lane < cnt) ? g_csr[base + lane] : 0;
        float mya = (lane < cnt) ? g_asrc2[my] : 0.f;
        for (int t = 0; t < cnt; t++) {
            int src  = __shfl_sync(0xffffffffu, my, t);
            float as = __shfl_sync(0xffffffffu, mya, t);
            float ev = __expf(leaky(as + adv));
            ssum += ev;
            acc  += ev * g_h2[(size_t)src * 32 + lane];
        }
    }
    {
        float evs = __expf(leaky(g_asrc2[w] + adv));
        ssum += evs;
        acc  += evs * g_h2[(size_t)w * 32 + lane];
    }
    acc = elu(acc / (ssum + 1e-16f) + b2[lane]);

    vsh[wl][lane] = acc;
    __syncwarp();
    if (lane < 16) {
        float o = bos[lane];
        #pragma unroll
        for (int c = 0; c < 32; c++) o += vsh[wl][c] * wos[c * 16 + lane];
        out[(size_t)w * FOUT + lane] = o;
    }
}

// ---------------- launch -----------------------------------------------------
extern "C" void kernel_launch(void* const* d_in, const int* in_sizes, int n_in,
                              void* d_out, int out_size) {
    const float* x        = (const float*)d_in[0];
    const int*   ei       = (const int*)d_in[1];
    const float* W1       = (const float*)d_in[2];
    const float* att_src1 = (const float*)d_in[3];
    const float* att_dst1 = (const float*)d_in[4];
    const float* b1       = (const float*)d_in[5];
    const float* W2       = (const float*)d_in[6];
    const float* att_src2 = (const float*)d_in[7];
    const float* att_dst2 = (const float*)d_in[8];
    const float* b2       = (const float*)d_in[9];
    const float* Wout     = (const float*)d_in[10];
    const float* bout     = (const float*)d_in[11];
    float*       out      = (float*)d_out;

    int n = in_sizes[0] / FIN;   // 50000
    int e = EFIX;                // 800000 (problem-fixed)

    // launch slot 4 = k_gemm1 (profiler lands there)
    k_detect <<<1, 1>>>(ei);
    k_zero   <<<(n + 255) / 256, 256>>>(n);
    k_count  <<<(e + 255) / 256, 256>>>(ei, e, n);
    dim3 g1((n + 127) / 128, 2);
    k_gemm1  <<<g1, 256>>>(x, W1, n);
    k_scanA  <<<NBLK, 256>>>(n);
    k_scanB  <<<1, 256>>>(NBLK, n);
    k_scanC  <<<NBLK, 256>>>(n);
    k_scatter<<<(e + 255) / 256, 256>>>(ei, e, n);

    k_attn1<<<(n + 7) / 8, 256>>>(att_src1, att_dst1, n);
    k_agg1 <<<(n + 7) / 8, 256>>>(b1, n);

    k_gemm2<<<(n + 15) / 16, 256>>>(W2, att_src2, att_dst2, n);
    k_agg2 <<<(n + 7) / 8, 256>>>(b2, Wout, bout, out, n);
}

// round 14
// speedup vs baseline: 1.4830x; 1.4830x over previous
#include <cuda_runtime.h>
#include <cuda_bf16.h>
#include <cuda_fp16.h>
#include <cstdint>
#include <math.h>

#define NMAX 50000
#define EFIX 800000
#define FIN  128
#define HC   256   // heads(8) * Hd(32)
#define H1   8
#define C2   32
#define FOUT 16
#define NBLK ((NMAX + 255) / 256)

// ---------------- scratch (static device globals; no allocation) -------------
__device__ float g_h1   [NMAX * HC];
__device__ __half2 g_h1h[NMAX * (HC / 2)];   // fp16 mirror for agg1 gather
__device__ float g_h1a  [NMAX * HC];
__device__ float g_asrc1[NMAX * H1];
__device__ float g_adst1[NMAX * H1];
__device__ float g_h2   [NMAX * C2];
__device__ float g_asrc2[NMAX];
__device__ float g_adst2[NMAX];
__device__ int   g_deg  [NMAX];
__device__ int   g_cur  [NMAX];
__device__ int   g_off  [NMAX + 1];
__device__ int   g_csr  [EFIX];
__device__ int   g_bsum [256];
__device__ int   g_bpre [256];
__device__ int   g_is64;

__device__ __forceinline__ float leaky(float x) { return x > 0.f ? x : 0.2f * x; }
__device__ __forceinline__ float elu(float x)   { return x > 0.f ? x : expm1f(x); }

// ---------------- tensor-core helpers ----------------------------------------
__device__ __forceinline__ unsigned smem_u32(const void* p) {
    unsigned addr;
    asm("{ .reg .u64 t; cvta.to.shared.u64 t, %1; cvt.u32.u64 %0, t; }"
        : "=r"(addr) : "l"(p));
    return addr;
}
__device__ __forceinline__ void ldsm_x4(unsigned& r0, unsigned& r1, unsigned& r2,
                                        unsigned& r3, unsigned addr) {
    asm volatile("ldmatrix.sync.aligned.m8n8.x4.shared.b16 {%0,%1,%2,%3}, [%4];"
                 : "=r"(r0), "=r"(r1), "=r"(r2), "=r"(r3) : "r"(addr));
}
__device__ __forceinline__ void ldsm_x4t(unsigned& r0, unsigned& r1, unsigned& r2,
                                         unsigned& r3, unsigned addr) {
    asm volatile("ldmatrix.sync.aligned.m8n8.x4.trans.shared.b16 {%0,%1,%2,%3}, [%4];"
                 : "=r"(r0), "=r"(r1), "=r"(r2), "=r"(r3) : "r"(addr));
}
__device__ __forceinline__ void mma_bf16(float* d, const unsigned* a,
                                         unsigned b0, unsigned b1) {
    asm volatile(
        "mma.sync.aligned.m16n8k16.row.col.f32.bf16.bf16.f32 "
        "{%0,%1,%2,%3}, {%4,%5,%6,%7}, {%8,%9}, {%0,%1,%2,%3};"
        : "+f"(d[0]), "+f"(d[1]), "+f"(d[2]), "+f"(d[3])
        : "r"(a[0]), "r"(a[1]), "r"(a[2]), "r"(a[3]), "r"(b0), "r"(b1));
}

// ---------------- dtype detection -------------------------------------------
__global__ void k_detect(const int* __restrict__ ei) {
    int z = 1;
    for (int i = 0; i < 64; i++)
        if (ei[2 * i + 1] != 0) { z = 0; break; }
    g_is64 = z;
}

// ---------------- CSR build --------------------------------------------------
__global__ void k_zero(int n) {
    int i = blockIdx.x * blockDim.x + threadIdx.x;
    if (i < n) { g_deg[i] = 0; g_cur[i] = 0; }
}

__global__ void k_count(const int* __restrict__ ei, int e, int n) {
    int i = blockIdx.x * blockDim.x + threadIdx.x;
    if (i < e) {
        int dst = g_is64 ? ei[2 * (e + i)] : ei[e + i];
        if ((unsigned)dst < (unsigned)n) atomicAdd(&g_deg[dst], 1);
    }
}

__global__ __launch_bounds__(256) void k_scanA(int n) {
    __shared__ int ws[8];
    int tid = threadIdx.x, lane = tid & 31, wid = tid >> 5;
    int idx = blockIdx.x * 256 + tid;
    int v = (idx < n) ? g_deg[idx] : 0;
    #pragma unroll
    for (int o = 16; o > 0; o >>= 1) v += __shfl_xor_sync(0xffffffffu, v, o);
    if (lane == 0) ws[wid] = v;
    __syncthreads();
    if (tid == 0) {
        int s = 0;
        #pragma unroll
        for (int i = 0; i < 8; i++) s += ws[i];
        g_bsum[blockIdx.x] = s;
    }
}

__global__ __launch_bounds__(256) void k_scanB(int nblk, int n) {
    __shared__ int wpre[8];
    int tid = threadIdx.x, lane = tid & 31, wid = tid >> 5;
    int v = (tid < nblk) ? g_bsum[tid] : 0;
    int inc = v;
    #pragma unroll
    for (int o = 1; o < 32; o <<= 1) {
        int t = __shfl_up_sync(0xffffffffu, inc, o);
        if (lane >= o) inc += t;
    }
    if (lane == 31) wpre[wid] = inc;
    __syncthreads();
    if (tid == 0) {
        int run = 0;
        #pragma unroll
        for (int i = 0; i < 8; i++) { int t = wpre[i]; wpre[i] = run; run += t; }
    }
    __syncthreads();
    int pre = inc - v + wpre[wid];
    if (tid < nblk) g_bpre[tid] = pre;
    if (tid == nblk - 1) g_off[n] = pre + v;
}

__global__ __launch_bounds__(256) void k_scanC(int n) {
    __shared__ int wpre[8];
    int tid = threadIdx.x, lane = tid & 31, wid = tid >> 5;
    int idx = blockIdx.x * 256 + tid;
    int v = (idx < n) ? g_deg[idx] : 0;
    int inc = v;
    #pragma unroll
    for (int o = 1; o < 32; o <<= 1) {
        int t = __shfl_up_sync(0xffffffffu, inc, o);
        if (lane >= o) inc += t;
    }
    if (lane == 31) wpre[wid] = inc;
    __syncthreads();
    if (tid == 0) {
        int run = 0;
        #pragma unroll
        for (int i = 0; i < 8; i++) { int t = wpre[i]; wpre[i] = run; run += t; }
    }
    __syncthreads();
    if (idx < n) g_off[idx] = g_bpre[blockIdx.x] + wpre[wid] + inc - v;
}

__global__ void k_scatter(const int* __restrict__ ei, int e, int n) {
    int i = blockIdx.x * blockDim.x + threadIdx.x;
    if (i < e) {
        int src, dst;
        if (g_is64) { src = ei[2 * i]; dst = ei[2 * (e + i)]; }
        else        { src = ei[i];     dst = ei[e + i]; }
        if ((unsigned)dst < (unsigned)n && (unsigned)src < (unsigned)n) {
            int pos = atomicAdd(&g_cur[dst], 1);
            g_csr[g_off[dst] + pos] = src;
        }
    }
}

// ---------------- GEMM1 (tensor cores): h1 = x @ W1 --------------------------
// bf16 m16n8k16 mma with 2-term split (hi+lo): acc = xh*wh + xh*wl + xl*wh.
// Epilogue writes fp32 h1 AND a packed-fp16 mirror (g_h1h) for agg1's gather.
#define XPAD 40
#define WPAD 136
__global__ __launch_bounds__(256) void k_gemm1(const float* __restrict__ x,
                                               const float* __restrict__ W, int n) {
    __shared__ __nv_bfloat16 xh[128][XPAD];
    __shared__ __nv_bfloat16 xl[128][XPAD];
    __shared__ __nv_bfloat16 wh[32][WPAD];
    __shared__ __nv_bfloat16 wl[32][WPAD];

    int row0 = blockIdx.x * 128;
    int col0 = blockIdx.y * 128;
    int t = threadIdx.x;
    int lane = t & 31, warp = t >> 5;
    int wr = (warp & 3) * 32;
    int wc = (warp >> 2) * 64;

    float acc[2][8][4];
    #pragma unroll
    for (int i = 0; i < 2; i++)
        #pragma unroll
        for (int j = 0; j < 8; j++)
            #pragma unroll
            for (int q = 0; q < 4; q++) acc[i][j][q] = 0.f;

    int grp = lane >> 3;
    int rIn = (lane & 7) + ((grp & 1) << 3);
    int cIn = (grp >> 1) << 3;

    for (int kc = 0; kc < FIN; kc += 32) {
        #pragma unroll
        for (int i = 0; i < 4; i++) {
            int f = t + i * 256;
            int r = f >> 3, kq = f & 7;
            int gr = row0 + r;
            float4 v = make_float4(0.f, 0.f, 0.f, 0.f);
            if (gr < n) v = *(const float4*)&x[(size_t)gr * FIN + kc + kq * 4];
            float vv[4] = {v.x, v.y, v.z, v.w};
            #pragma unroll
            for (int j = 0; j < 4; j++) {
                __nv_bfloat16 hi = __float2bfloat16(vv[j]);
                xh[r][kq * 4 + j] = hi;
                xl[r][kq * 4 + j] = __float2bfloat16(vv[j] - __bfloat162float(hi));
            }
        }
        #pragma unroll
        for (int i = 0; i < 4; i++) {
            int f = t + i * 256;
            int k = f >> 5, c4 = f & 31;
            float4 v = *(const float4*)&W[(size_t)(kc + k) * HC + col0 + c4 * 4];
            float vv[4] = {v.x, v.y, v.z, v.w};
            #pragma unroll
            for (int j = 0; j < 4; j++) {
                __nv_bfloat16 hi = __float2bfloat16(vv[j]);
                wh[k][c4 * 4 + j] = hi;
                wl[k][c4 * 4 + j] = __float2bfloat16(vv[j] - __bfloat162float(hi));
            }
        }
        __syncthreads();

        #pragma unroll
        for (int k16 = 0; k16 < 32; k16 += 16) {
            unsigned Ah[2][4], Al[2][4];
            #pragma unroll
            for (int tt = 0; tt < 2; tt++) {
                int row = wr + tt * 16 + rIn;
                int col = k16 + cIn;
                ldsm_x4(Ah[tt][0], Ah[tt][1], Ah[tt][2], Ah[tt][3],
                        smem_u32(&xh[row][col]));
                ldsm_x4(Al[tt][0], Al[tt][1], Al[tt][2], Al[tt][3],
                        smem_u32(&xl[row][col]));
            }
            #pragma unroll
            for (int p = 0; p < 4; p++) {
                int row = k16 + rIn;
                int col = wc + p * 16 + cIn;
                unsigned Bh[4], Bl[4];
                ldsm_x4t(Bh[0], Bh[1], Bh[2], Bh[3], smem_u32(&wh[row][col]));
                ldsm_x4t(Bl[0], Bl[1], Bl[2], Bl[3], smem_u32(&wl[row][col]));
                #pragma unroll
                for (int tt = 0; tt < 2; tt++) {
                    #pragma unroll
                    for (int q = 0; q < 2; q++) {
                        float* d = acc[tt][p * 2 + q];
                        mma_bf16(d, Ah[tt], Bh[2 * q], Bh[2 * q + 1]);
                        mma_bf16(d, Ah[tt], Bl[2 * q], Bl[2 * q + 1]);
                        mma_bf16(d, Al[tt], Bh[2 * q], Bh[2 * q + 1]);
                    }
                }
            }
        }
        __syncthreads();
    }

    #pragma unroll
    for (int tt = 0; tt < 2; tt++) {
        #pragma unroll
        for (int j = 0; j < 8; j++) {
            int gr = row0 + wr + tt * 16 + (lane >> 2);
            int gc = col0 + wc + j * 8 + (lane & 3) * 2;
            if (gr < n) {
                *(float2*)&g_h1[(size_t)gr * HC + gc] =
                    make_float2(acc[tt][j][0], acc[tt][j][1]);
                g_h1h[(size_t)gr * (HC / 2) + (gc >> 1)] =
                    __floats2half2_rn(acc[tt][j][0], acc[tt][j][1]);
            }
            if (gr + 8 < n) {
                *(float2*)&g_h1[(size_t)(gr + 8) * HC + gc] =
                    make_float2(acc[tt][j][2], acc[tt][j][3]);
                g_h1h[(size_t)(gr + 8) * (HC / 2) + (gc >> 1)] =
                    __floats2half2_rn(acc[tt][j][2], acc[tt][j][3]);
            }
        }
    }
}

// ---------------- attention scores layer 1 (warp per node) -------------------
__global__ __launch_bounds__(256) void k_attn1(const float* __restrict__ as,
                                               const float* __restrict__ adv, int n) {
    __shared__ float s_s[HC], s_d[HC];
    if (threadIdx.x < HC) { s_s[threadIdx.x] = as[threadIdx.x]; s_d[threadIdx.x] = adv[threadIdx.x]; }
    __syncthreads();
    int w = (blockIdx.x * blockDim.x + threadIdx.x) >> 5;
    int lane = threadIdx.x & 31;
    if (w >= n) return;
    float4 v0 = *(const float4*)&g_h1[(size_t)w * HC + lane * 8];
    float4 v1 = *(const float4*)&g_h1[(size_t)w * HC + lane * 8 + 4];
    const float* ss = &s_s[lane * 8];
    const float* sd = &s_d[lane * 8];
    float ps = v0.x*ss[0] + v0.y*ss[1] + v0.z*ss[2] + v0.w*ss[3]
             + v1.x*ss[4] + v1.y*ss[5] + v1.z*ss[6] + v1.w*ss[7];
    float pd = v0.x*sd[0] + v0.y*sd[1] + v0.z*sd[2] + v0.w*sd[3]
             + v1.x*sd[4] + v1.y*sd[5] + v1.z*sd[6] + v1.w*sd[7];
    ps += __shfl_xor_sync(0xffffffffu, ps, 1);
    pd += __shfl_xor_sync(0xffffffffu, pd, 1);
    ps += __shfl_xor_sync(0xffffffffu, ps, 2);
    pd += __shfl_xor_sync(0xffffffffu, pd, 2);
    if ((lane & 3) == 0) {
        g_asrc1[w * H1 + (lane >> 2)] = ps;
        g_adst1[w * H1 + (lane >> 2)] = pd;
    }
}

// ---------------- layer-1 aggregation + ELU (single pass, fp16 gather) -------
__global__ __launch_bounds__(256) void k_agg1(const float* __restrict__ b1, int n) {
    int w = (blockIdx.x * blockDim.x + threadIdx.x) >> 5;
    int lane = threadIdx.x & 31;
    if (w >= n) return;
    int beg = g_off[w], end = g_off[w + 1];

    int h1i = lane >> 3;
    int h2i = 4 + h1i;
    float adh1 = g_adst1[w * H1 + h1i];
    float adh2 = g_adst1[w * H1 + h2i];

    float ssum1 = 0.f, ssum2 = 0.f;
    float4 acc1 = make_float4(0.f, 0.f, 0.f, 0.f);
    float4 acc2 = make_float4(0.f, 0.f, 0.f, 0.f);

    for (int base = beg; base < end; base += 32) {
        int cnt = end - base; if (cnt > 32) cnt = 32;
        int my = (lane < cnt) ? g_csr[base + lane] : 0;
        for (int t = 0; t < cnt; t++) {
            int src = __shfl_sync(0xffffffffu, my, t);
            float ev1 = __expf(leaky(g_asrc1[src * H1 + h1i] + adh1));
            float ev2 = __expf(leaky(g_asrc1[src * H1 + h2i] + adh2));
            ssum1 += ev1; ssum2 += ev2;
            uint2 q1 = *(const uint2*)(g_h1h + (size_t)src * (HC / 2) + lane * 2);
            uint2 q2 = *(const uint2*)(g_h1h + (size_t)src * (HC / 2) + 64 + lane * 2);
            float2 a = __half22float2(*(__half2*)&q1.x);
            float2 b = __half22float2(*(__half2*)&q1.y);
            float2 c = __half22float2(*(__half2*)&q2.x);
            float2 d = __half22float2(*(__half2*)&q2.y);
            acc1.x += ev1 * a.x; acc1.y += ev1 * a.y; acc1.z += ev1 * b.x; acc1.w += ev1 * b.y;
            acc2.x += ev2 * c.x; acc2.y += ev2 * c.y; acc2.z += ev2 * d.x; acc2.w += ev2 * d.y;
        }
    }
    {
        float es1 = __expf(leaky(g_asrc1[w * H1 + h1i] + adh1));
        float es2 = __expf(leaky(g_asrc1[w * H1 + h2i] + adh2));
        ssum1 += es1; ssum2 += es2;
        uint2 q1 = *(const uint2*)(g_h1h + (size_t)w * (HC / 2) + lane * 2);
        uint2 q2 = *(const uint2*)(g_h1h + (size_t)w * (HC / 2) + 64 + lane * 2);
        float2 a = __half22float2(*(__half2*)&q1.x);
        float2 b = __half22float2(*(__half2*)&q1.y);
        float2 c = __half22float2(*(__half2*)&q2.x);
        float2 d = __half22float2(*(__half2*)&q2.y);
        acc1.x += es1 * a.x; acc1.y += es1 * a.y; acc1.z += es1 * b.x; acc1.w += es1 * b.y;
        acc2.x += es2 * c.x; acc2.y += es2 * c.y; acc2.z += es2 * d.x; acc2.w += es2 * d.y;
    }
    float iv1 = 1.f / (ssum1 + 1e-16f);
    float iv2 = 1.f / (ssum2 + 1e-16f);
    float4 bb1 = *(const float4*)&b1[lane * 4];
    float4 bb2 = *(const float4*)&b1[128 + lane * 4];
    acc1.x = elu(acc1.x * iv1 + bb1.x); acc1.y = elu(acc1.y * iv1 + bb1.y);
    acc1.z = elu(acc1.z * iv1 + bb1.z); acc1.w = elu(acc1.w * iv1 + bb1.w);
    acc2.x = elu(acc2.x * iv2 + bb2.x); acc2.y = elu(acc2.y * iv2 + bb2.y);
    acc2.z = elu(acc2.z * iv2 + bb2.z); acc2.w = elu(acc2.w * iv2 + bb2.w);
    *(float4*)&g_h1a[(size_t)w * HC + lane * 4]       = acc1;
    *(float4*)&g_h1a[(size_t)w * HC + 128 + lane * 4] = acc2;
}

// ---------------- GEMM2 (+ fused attn2): h2 = h1a @ W2 -----------------------
__global__ __launch_bounds__(256) void k_gemm2(const float* __restrict__ W2,
                                               const float* __restrict__ att_s2,
                                               const float* __restrict__ att_d2, int n) {
    __shared__ float w2s[256 * 32];
    __shared__ float hs[16 * 256];
    __shared__ float a2s[32], a2d[32];
    int t = threadIdx.x;
    if (t < 32) { a2s[t] = att_s2[t]; a2d[t] = att_d2[t]; }
    #pragma unroll
    for (int i = 0; i < 8; i++)
        ((float4*)w2s)[t + i * 256] = ((const float4*)W2)[t + i * 256];
    int row0 = blockIdx.x * 16;
    #pragma unroll
    for (int i = 0; i < 4; i++) {
        int f = t + i * 256;
        int r = f >> 6, c4 = f & 63;
        int gr = row0 + r;
        float4 v = make_float4(0.f, 0.f, 0.f, 0.f);
        if (gr < n) v = ((const float4*)&g_h1a[(size_t)gr * HC])[c4];
        ((float4*)hs)[f] = v;
    }
    __syncthreads();
    int col = t & 31, rg = t >> 5;
    float acc0 = 0.f, acc1 = 0.f;
    for (int k = 0; k < 256; k += 4) {
        float b0 = w2s[k * 32 + col];
        float b1 = w2s[(k + 1) * 32 + col];
        float b2 = w2s[(k + 2) * 32 + col];
        float b3 = w2s[(k + 3) * 32 + col];
        float4 a0 = *(float4*)&hs[rg * 256 + k];
        float4 a1 = *(float4*)&hs[(rg + 8) * 256 + k];
        acc0 += a0.x * b0 + a0.y * b1 + a0.z * b2 + a0.w * b3;
        acc1 += a1.x * b0 + a1.y * b1 + a1.z * b2 + a1.w * b3;
    }
    int gr0 = row0 + rg, gr1 = row0 + rg + 8;
    if (gr0 < n) g_h2[(size_t)gr0 * 32 + col] = acc0;
    if (gr1 < n) g_h2[(size_t)gr1 * 32 + col] = acc1;
    float s0 = acc0 * a2s[col], d0 = acc0 * a2d[col];
    float s1 = acc1 * a2s[col], d1 = acc1 * a2d[col];
    #pragma unroll
    for (int o = 16; o > 0; o >>= 1) {
        s0 += __shfl_xor_sync(0xffffffffu, s0, o);
        d0 += __shfl_xor_sync(0xffffffffu, d0, o);
        s1 += __shfl_xor_sync(0xffffffffu, s1, o);
        d1 += __shfl_xor_sync(0xffffffffu, d1, o);
    }
    if (col == 0) {
        if (gr0 < n) { g_asrc2[gr0] = s0; g_adst2[gr0] = d0; }
        if (gr1 < n) { g_asrc2[gr1] = s1; g_adst2[gr1] = d1; }
    }
}

// ---------------- layer-2 agg (single pass) + ELU + (@Wout + bout) -----------
__global__ __launch_bounds__(256) void k_agg2(const float* __restrict__ b2,
                                              const float* __restrict__ Wout,
                                              const float* __restrict__ bout,
                                              float* __restrict__ out, int n) {
    __shared__ float wos[32 * 16];
    __shared__ float bos[16];
    __shared__ float vsh[8][32];
    wos[threadIdx.x]       = Wout[threadIdx.x];
    wos[threadIdx.x + 256] = Wout[threadIdx.x + 256];
    if (threadIdx.x < 16)  bos[threadIdx.x] = bout[threadIdx.x];
    __syncthreads();

    int w = (blockIdx.x * blockDim.x + threadIdx.x) >> 5;
    int lane = threadIdx.x & 31;
    int wl = threadIdx.x >> 5;
    if (w >= n) return;

    float adv = g_adst2[w];
    int beg = g_off[w], end = g_off[w + 1];

    float ssum = 0.f, acc = 0.f;
    for (int base = beg; base < end; base += 32) {
        int cnt = end - base; if (cnt > 32) cnt = 32;
        int my = (lane < cnt) ? g_csr[base + lane] : 0;
        float mya = (lane < cnt) ? g_asrc2[my] : 0.f;
        for (int t = 0; t < cnt; t++) {
            int src  = __shfl_sync(0xffffffffu, my, t);
            float as = __shfl_sync(0xffffffffu, mya, t);
            float ev = __expf(leaky(as + adv));
            ssum += ev;
            acc  += ev * g_h2[(size_t)src * 32 + lane];
        }
    }
    {
        float evs = __expf(leaky(g_asrc2[w] + adv));
        ssum += evs;
        acc  += evs * g_h2[(size_t)w * 32 + lane];
    }
    acc = elu(acc / (ssum + 1e-16f) + b2[lane]);

    vsh[wl][lane] = acc;
    __syncwarp();
    if (lane < 16) {
        float o = bos[lane];
        #pragma unroll
        for (int c = 0; c < 32; c++) o += vsh[wl][c] * wos[c * 16 + lane];
        out[(size_t)w * FOUT + lane] = o;
    }
}

// ---------------- launch -----------------------------------------------------
extern "C" void kernel_launch(void* const* d_in, const int* in_sizes, int n_in,
                              void* d_out, int out_size) {
    const float* x        = (const float*)d_in[0];
    const int*   ei       = (const int*)d_in[1];
    const float* W1       = (const float*)d_in[2];
    const float* att_src1 = (const float*)d_in[3];
    const float* att_dst1 = (const float*)d_in[4];
    const float* b1       = (const float*)d_in[5];
    const float* W2       = (const float*)d_in[6];
    const float* att_src2 = (const float*)d_in[7];
    const float* att_dst2 = (const float*)d_in[8];
    const float* b2       = (const float*)d_in[9];
    const float* Wout     = (const float*)d_in[10];
    const float* bout     = (const float*)d_in[11];
    float*       out      = (float*)d_out;

    int n = in_sizes[0] / FIN;   // 50000
    int e = EFIX;                // 800000 (problem-fixed)

    // launch slot 4 = k_gemm1 (profiler lands there)
    k_detect <<<1, 1>>>(ei);
    k_zero   <<<(n + 255) / 256, 256>>>(n);
    k_count  <<<(e + 255) / 256, 256>>>(ei, e, n);
    dim3 g1((n + 127) / 128, 2);
    k_gemm1  <<<g1, 256>>>(x, W1, n);
    k_scanA  <<<NBLK, 256>>>(n);
    k_scanB  <<<1, 256>>>(NBLK, n);
    k_scanC  <<<NBLK, 256>>>(n);
    k_scatter<<<(e + 255) / 256, 256>>>(ei, e, n);

    k_attn1<<<(n + 7) / 8, 256>>>(att_src1, att_dst1, n);
    k_agg1 <<<(n + 7) / 8, 256>>>(b1, n);

    k_gemm2<<<(n + 15) / 16, 256>>>(W2, att_src2, att_dst2, n);
    k_agg2 <<<(n + 7) / 8, 256>>>(b2, Wout, bout, out, n);
}

// round 15
// speedup vs baseline: 1.6080x; 1.0843x over previous
#include <cuda_runtime.h>
#include <cuda_bf16.h>
#include <cuda_fp16.h>
#include <cstdint>
#include <math.h>

#define NMAX 50000
#define EFIX 800000
#define FIN  128
#define HC   256   // heads(8) * Hd(32)
#define H1   8
#define C2   32
#define FOUT 16
#define NBLK ((NMAX + 255) / 256)

// ---------------- scratch (static device globals; no allocation) -------------
__device__ __half2 g_h1h[NMAX * (HC / 2)];   // fp16 h1 (sole copy; agg1 gathers it)
__device__ float g_h1a  [NMAX * HC];
__device__ float g_asrc1[NMAX * H1];
__device__ float g_adst1[NMAX * H1];
__device__ float g_h2   [NMAX * C2];
__device__ float g_asrc2[NMAX];
__device__ float g_adst2[NMAX];
__device__ int   g_deg  [NMAX];
__device__ int   g_cur  [NMAX];
__device__ int   g_off  [NMAX + 1];
__device__ int   g_csr  [EFIX];
__device__ int   g_bsum [256];
__device__ int   g_bpre [256];
__device__ int   g_is64;

__device__ __forceinline__ float leaky(float x) { return x > 0.f ? x : 0.2f * x; }
__device__ __forceinline__ float elu(float x)   { return x > 0.f ? x : expm1f(x); }

// ---------------- tensor-core helpers ----------------------------------------
__device__ __forceinline__ unsigned smem_u32(const void* p) {
    unsigned addr;
    asm("{ .reg .u64 t; cvta.to.shared.u64 t, %1; cvt.u32.u64 %0, t; }"
        : "=r"(addr) : "l"(p));
    return addr;
}
__device__ __forceinline__ void ldsm_x4(unsigned& r0, unsigned& r1, unsigned& r2,
                                        unsigned& r3, unsigned addr) {
    asm volatile("ldmatrix.sync.aligned.m8n8.x4.shared.b16 {%0,%1,%2,%3}, [%4];"
                 : "=r"(r0), "=r"(r1), "=r"(r2), "=r"(r3) : "r"(addr));
}
__device__ __forceinline__ void ldsm_x4t(unsigned& r0, unsigned& r1, unsigned& r2,
                                         unsigned& r3, unsigned addr) {
    asm volatile("ldmatrix.sync.aligned.m8n8.x4.trans.shared.b16 {%0,%1,%2,%3}, [%4];"
                 : "=r"(r0), "=r"(r1), "=r"(r2), "=r"(r3) : "r"(addr));
}
__device__ __forceinline__ void mma_bf16(float* d, const unsigned* a,
                                         unsigned b0, unsigned b1) {
    asm volatile(
        "mma.sync.aligned.m16n8k16.row.col.f32.bf16.bf16.f32 "
        "{%0,%1,%2,%3}, {%4,%5,%6,%7}, {%8,%9}, {%0,%1,%2,%3};"
        : "+f"(d[0]), "+f"(d[1]), "+f"(d[2]), "+f"(d[3])
        : "r"(a[0]), "r"(a[1]), "r"(a[2]), "r"(a[3]), "r"(b0), "r"(b1));
}

// ---------------- dtype detection -------------------------------------------
__global__ void k_detect(const int* __restrict__ ei) {
    int z = 1;
    for (int i = 0; i < 64; i++)
        if (ei[2 * i + 1] != 0) { z = 0; break; }
    g_is64 = z;
}

// ---------------- CSR build --------------------------------------------------
__global__ void k_zero(int n) {
    int i = blockIdx.x * blockDim.x + threadIdx.x;
    if (i < n) { g_deg[i] = 0; g_cur[i] = 0; }
}

__global__ void k_count(const int* __restrict__ ei, int e, int n) {
    int i = blockIdx.x * blockDim.x + threadIdx.x;
    if (i < e) {
        int dst = g_is64 ? ei[2 * (e + i)] : ei[e + i];
        if ((unsigned)dst < (unsigned)n) atomicAdd(&g_deg[dst], 1);
    }
}

__global__ __launch_bounds__(256) void k_scanA(int n) {
    __shared__ int ws[8];
    int tid = threadIdx.x, lane = tid & 31, wid = tid >> 5;
    int idx = blockIdx.x * 256 + tid;
    int v = (idx < n) ? g_deg[idx] : 0;
    #pragma unroll
    for (int o = 16; o > 0; o >>= 1) v += __shfl_xor_sync(0xffffffffu, v, o);
    if (lane == 0) ws[wid] = v;
    __syncthreads();
    if (tid == 0) {
        int s = 0;
        #pragma unroll
        for (int i = 0; i < 8; i++) s += ws[i];
        g_bsum[blockIdx.x] = s;
    }
}

__global__ __launch_bounds__(256) void k_scanB(int nblk, int n) {
    __shared__ int wpre[8];
    int tid = threadIdx.x, lane = tid & 31, wid = tid >> 5;
    int v = (tid < nblk) ? g_bsum[tid] : 0;
    int inc = v;
    #pragma unroll
    for (int o = 1; o < 32; o <<= 1) {
        int t = __shfl_up_sync(0xffffffffu, inc, o);
        if (lane >= o) inc += t;
    }
    if (lane == 31) wpre[wid] = inc;
    __syncthreads();
    if (tid == 0) {
        int run = 0;
        #pragma unroll
        for (int i = 0; i < 8; i++) { int t = wpre[i]; wpre[i] = run; run += t; }
    }
    __syncthreads();
    int pre = inc - v + wpre[wid];
    if (tid < nblk) g_bpre[tid] = pre;
    if (tid == nblk - 1) g_off[n] = pre + v;
}

__global__ __launch_bounds__(256) void k_scanC(int n) {
    __shared__ int wpre[8];
    int tid = threadIdx.x, lane = tid & 31, wid = tid >> 5;
    int idx = blockIdx.x * 256 + tid;
    int v = (idx < n) ? g_deg[idx] : 0;
    int inc = v;
    #pragma unroll
    for (int o = 1; o < 32; o <<= 1) {
        int t = __shfl_up_sync(0xffffffffu, inc, o);
        if (lane >= o) inc += t;
    }
    if (lane == 31) wpre[wid] = inc;
    __syncthreads();
    if (tid == 0) {
        int run = 0;
        #pragma unroll
        for (int i = 0; i < 8; i++) { int t = wpre[i]; wpre[i] = run; run += t; }
    }
    __syncthreads();
    if (idx < n) g_off[idx] = g_bpre[blockIdx.x] + wpre[wid] + inc - v;
}

__global__ void k_scatter(const int* __restrict__ ei, int e, int n) {
    int i = blockIdx.x * blockDim.x + threadIdx.x;
    if (i < e) {
        int src, dst;
        if (g_is64) { src = ei[2 * i]; dst = ei[2 * (e + i)]; }
        else        { src = ei[i];     dst = ei[e + i]; }
        if ((unsigned)dst < (unsigned)n && (unsigned)src < (unsigned)n) {
            int pos = atomicAdd(&g_cur[dst], 1);
            g_csr[g_off[dst] + pos] = src;
        }
    }
}

// ---------------- GEMM1 (tensor cores) + fused attn1 -------------------------
// bf16 m16n8k16 mma with 2-term split. Epilogue:
//  - stores ONLY the packed-fp16 h1 (g_h1h)
//  - computes a_src1/a_dst1 per (row, head) from the exact fp32 accumulators:
//    each head's 32 channels live inside this CTA tile; a row's 64 warp-cols
//    sit in 4 lanes -> 2x shfl_xor reduce over lane&3.
#define XPAD 40
#define WPAD 136
__global__ __launch_bounds__(256) void k_gemm1(const float* __restrict__ x,
                                               const float* __restrict__ W,
                                               const float* __restrict__ att_s,
                                               const float* __restrict__ att_d, int n) {
    __shared__ __nv_bfloat16 xh[128][XPAD];
    __shared__ __nv_bfloat16 xl[128][XPAD];
    __shared__ __nv_bfloat16 wh[32][WPAD];
    __shared__ __nv_bfloat16 wl[32][WPAD];
    __shared__ float s_as[HC], s_ad[HC];

    int row0 = blockIdx.x * 128;
    int col0 = blockIdx.y * 128;
    int t = threadIdx.x;
    int lane = t & 31, warp = t >> 5;
    int wr = (warp & 3) * 32;
    int wc = (warp >> 2) * 64;

    if (t < HC) { s_as[t] = att_s[t]; s_ad[t] = att_d[t]; }

    float acc[2][8][4];
    #pragma unroll
    for (int i = 0; i < 2; i++)
        #pragma unroll
        for (int j = 0; j < 8; j++)
            #pragma unroll
            for (int q = 0; q < 4; q++) acc[i][j][q] = 0.f;

    int grp = lane >> 3;
    int rIn = (lane & 7) + ((grp & 1) << 3);
    int cIn = (grp >> 1) << 3;

    for (int kc = 0; kc < FIN; kc += 32) {
        #pragma unroll
        for (int i = 0; i < 4; i++) {
            int f = t + i * 256;
            int r = f >> 3, kq = f & 7;
            int gr = row0 + r;
            float4 v = make_float4(0.f, 0.f, 0.f, 0.f);
            if (gr < n) v = *(const float4*)&x[(size_t)gr * FIN + kc + kq * 4];
            float vv[4] = {v.x, v.y, v.z, v.w};
            #pragma unroll
            for (int j = 0; j < 4; j++) {
                __nv_bfloat16 hi = __float2bfloat16(vv[j]);
                xh[r][kq * 4 + j] = hi;
                xl[r][kq * 4 + j] = __float2bfloat16(vv[j] - __bfloat162float(hi));
            }
        }
        #pragma unroll
        for (int i = 0; i < 4; i++) {
            int f = t + i * 256;
            int k = f >> 5, c4 = f & 31;
            float4 v = *(const float4*)&W[(size_t)(kc + k) * HC + col0 + c4 * 4];
            float vv[4] = {v.x, v.y, v.z, v.w};
            #pragma unroll
            for (int j = 0; j < 4; j++) {
                __nv_bfloat16 hi = __float2bfloat16(vv[j]);
                wh[k][c4 * 4 + j] = hi;
                wl[k][c4 * 4 + j] = __float2bfloat16(vv[j] - __bfloat162float(hi));
            }
        }
        __syncthreads();

        #pragma unroll
        for (int k16 = 0; k16 < 32; k16 += 16) {
            unsigned Ah[2][4], Al[2][4];
            #pragma unroll
            for (int tt = 0; tt < 2; tt++) {
                int row = wr + tt * 16 + rIn;
                int col = k16 + cIn;
                ldsm_x4(Ah[tt][0], Ah[tt][1], Ah[tt][2], Ah[tt][3],
                        smem_u32(&xh[row][col]));
                ldsm_x4(Al[tt][0], Al[tt][1], Al[tt][2], Al[tt][3],
                        smem_u32(&xl[row][col]));
            }
            #pragma unroll
            for (int p = 0; p < 4; p++) {
                int row = k16 + rIn;
                int col = wc + p * 16 + cIn;
                unsigned Bh[4], Bl[4];
                ldsm_x4t(Bh[0], Bh[1], Bh[2], Bh[3], smem_u32(&wh[row][col]));
                ldsm_x4t(Bl[0], Bl[1], Bl[2], Bl[3], smem_u32(&wl[row][col]));
                #pragma unroll
                for (int tt = 0; tt < 2; tt++) {
                    #pragma unroll
                    for (int q = 0; q < 2; q++) {
                        float* d = acc[tt][p * 2 + q];
                        mma_bf16(d, Ah[tt], Bh[2 * q], Bh[2 * q + 1]);
                        mma_bf16(d, Ah[tt], Bl[2 * q], Bl[2 * q + 1]);
                        mma_bf16(d, Al[tt], Bh[2 * q], Bh[2 * q + 1]);
                    }
                }
            }
        }
        __syncthreads();
    }

    // epilogue: fp16 h1 store + fused attn1
    int hd0 = (col0 + wc) >> 5;   // global head of warp's first 32 cols
    #pragma unroll
    for (int tt = 0; tt < 2; tt++) {
        int gr0r = row0 + wr + tt * 16 + (lane >> 2);
        #pragma unroll
        for (int j = 0; j < 8; j++) {
            int gc = col0 + wc + j * 8 + (lane & 3) * 2;
            if (gr0r < n)
                g_h1h[(size_t)gr0r * (HC / 2) + (gc >> 1)] =
                    __floats2half2_rn(acc[tt][j][0], acc[tt][j][1]);
            if (gr0r + 8 < n)
                g_h1h[(size_t)(gr0r + 8) * (HC / 2) + (gc >> 1)] =
                    __floats2half2_rn(acc[tt][j][2], acc[tt][j][3]);
        }
        // attn1 partials: head h (local 0/1) = j in [4h, 4h+4)
        #pragma unroll
        for (int h = 0; h < 2; h++) {
            float psA = 0.f, pdA = 0.f, psB = 0.f, pdB = 0.f;
            #pragma unroll
            for (int jj = 0; jj < 4; jj++) {
                int j = h * 4 + jj;
                int c = col0 + wc + j * 8 + (lane & 3) * 2;
                float a0 = s_as[c], a1 = s_as[c + 1];
                float d0 = s_ad[c], d1 = s_ad[c + 1];
                psA += acc[tt][j][0] * a0 + acc[tt][j][1] * a1;
                pdA += acc[tt][j][0] * d0 + acc[tt][j][1] * d1;
                psB += acc[tt][j][2] * a0 + acc[tt][j][3] * a1;
                pdB += acc[tt][j][2] * d0 + acc[tt][j][3] * d1;
            }
            psA += __shfl_xor_sync(0xffffffffu, psA, 1);
            pdA += __shfl_xor_sync(0xffffffffu, pdA, 1);
            psB += __shfl_xor_sync(0xffffffffu, psB, 1);
            pdB += __shfl_xor_sync(0xffffffffu, pdB, 1);
            psA += __shfl_xor_sync(0xffffffffu, psA, 2);
            pdA += __shfl_xor_sync(0xffffffffu, pdA, 2);
            psB += __shfl_xor_sync(0xffffffffu, psB, 2);
            pdB += __shfl_xor_sync(0xffffffffu, pdB, 2);
            if ((lane & 3) == 0) {
                int gh = hd0 + h;
                if (gr0r < n) {
                    g_asrc1[gr0r * H1 + gh] = psA;
                    g_adst1[gr0r * H1 + gh] = pdA;
                }
                if (gr0r + 8 < n) {
                    g_asrc1[(gr0r + 8) * H1 + gh] = psB;
                    g_adst1[(gr0r + 8) * H1 + gh] = pdB;
                }
            }
        }
    }
}

// ---------------- layer-1 aggregation + ELU (single pass, fp16 gather) -------
__global__ __launch_bounds__(256) void k_agg1(const float* __restrict__ b1, int n) {
    int w = (blockIdx.x * blockDim.x + threadIdx.x) >> 5;
    int lane = threadIdx.x & 31;
    if (w >= n) return;
    int beg = g_off[w], end = g_off[w + 1];

    int h1i = lane >> 3;
    int h2i = 4 + h1i;
    float adh1 = g_adst1[w * H1 + h1i];
    float adh2 = g_adst1[w * H1 + h2i];

    float ssum1 = 0.f, ssum2 = 0.f;
    float4 acc1 = make_float4(0.f, 0.f, 0.f, 0.f);
    float4 acc2 = make_float4(0.f, 0.f, 0.f, 0.f);

    for (int base = beg; base < end; base += 32) {
        int cnt = end - base; if (cnt > 32) cnt = 32;
        int my = (lane < cnt) ? g_csr[base + lane] : 0;
        for (int t = 0; t < cnt; t++) {
            int src = __shfl_sync(0xffffffffu, my, t);
            float ev1 = __expf(leaky(g_asrc1[src * H1 + h1i] + adh1));
            float ev2 = __expf(leaky(g_asrc1[src * H1 + h2i] + adh2));
            ssum1 += ev1; ssum2 += ev2;
            uint2 q1 = *(const uint2*)(g_h1h + (size_t)src * (HC / 2) + lane * 2);
            uint2 q2 = *(const uint2*)(g_h1h + (size_t)src * (HC / 2) + 64 + lane * 2);
            float2 a = __half22float2(*(__half2*)&q1.x);
            float2 b = __half22float2(*(__half2*)&q1.y);
            float2 c = __half22float2(*(__half2*)&q2.x);
            float2 d = __half22float2(*(__half2*)&q2.y);
            acc1.x += ev1 * a.x; acc1.y += ev1 * a.y; acc1.z += ev1 * b.x; acc1.w += ev1 * b.y;
            acc2.x += ev2 * c.x; acc2.y += ev2 * c.y; acc2.z += ev2 * d.x; acc2.w += ev2 * d.y;
        }
    }
    {
        float es1 = __expf(leaky(g_asrc1[w * H1 + h1i] + adh1));
        float es2 = __expf(leaky(g_asrc1[w * H1 + h2i] + adh2));
        ssum1 += es1; ssum2 += es2;
        uint2 q1 = *(const uint2*)(g_h1h + (size_t)w * (HC / 2) + lane * 2);
        uint2 q2 = *(const uint2*)(g_h1h + (size_t)w * (HC / 2) + 64 + lane * 2);
        float2 a = __half22float2(*(__half2*)&q1.x);
        float2 b = __half22float2(*(__half2*)&q1.y);
        float2 c = __half22float2(*(__half2*)&q2.x);
        float2 d = __half22float2(*(__half2*)&q2.y);
        acc1.x += es1 * a.x; acc1.y += es1 * a.y; acc1.z += es1 * b.x; acc1.w += es1 * b.y;
        acc2.x += es2 * c.x; acc2.y += es2 * c.y; acc2.z += es2 * d.x; acc2.w += es2 * d.y;
    }
    float iv1 = 1.f / (ssum1 + 1e-16f);
    float iv2 = 1.f / (ssum2 + 1e-16f);
    float4 bb1 = *(const float4*)&b1[lane * 4];
    float4 bb2 = *(const float4*)&b1[128 + lane * 4];
    acc1.x = elu(acc1.x * iv1 + bb1.x); acc1.y = elu(acc1.y * iv1 + bb1.y);
    acc1.z = elu(acc1.z * iv1 + bb1.z); acc1.w = elu(acc1.w * iv1 + bb1.w);
    acc2.x = elu(acc2.x * iv2 + bb2.x); acc2.y = elu(acc2.y * iv2 + bb2.y);
    acc2.z = elu(acc2.z * iv2 + bb2.z); acc2.w = elu(acc2.w * iv2 + bb2.w);
    *(float4*)&g_h1a[(size_t)w * HC + lane * 4]       = acc1;
    *(float4*)&g_h1a[(size_t)w * HC + 128 + lane * 4] = acc2;
}

// ---------------- GEMM2 (+ fused attn2): h2 = h1a @ W2 -----------------------
__global__ __launch_bounds__(256) void k_gemm2(const float* __restrict__ W2,
                                               const float* __restrict__ att_s2,
                                               const float* __restrict__ att_d2, int n) {
    __shared__ float w2s[256 * 32];
    __shared__ float hs[16 * 256];
    __shared__ float a2s[32], a2d[32];
    int t = threadIdx.x;
    if (t < 32) { a2s[t] = att_s2[t]; a2d[t] = att_d2[t]; }
    #pragma unroll
    for (int i = 0; i < 8; i++)
        ((float4*)w2s)[t + i * 256] = ((const float4*)W2)[t + i * 256];
    int row0 = blockIdx.x * 16;
    #pragma unroll
    for (int i = 0; i < 4; i++) {
        int f = t + i * 256;
        int r = f >> 6, c4 = f & 63;
        int gr = row0 + r;
        float4 v = make_float4(0.f, 0.f, 0.f, 0.f);
        if (gr < n) v = ((const float4*)&g_h1a[(size_t)gr * HC])[c4];
        ((float4*)hs)[f] = v;
    }
    __syncthreads();
    int col = t & 31, rg = t >> 5;
    float acc0 = 0.f, acc1 = 0.f;
    for (int k = 0; k < 256; k += 4) {
        float b0 = w2s[k * 32 + col];
        float b1 = w2s[(k + 1) * 32 + col];
        float b2 = w2s[(k + 2) * 32 + col];
        float b3 = w2s[(k + 3) * 32 + col];
        float4 a0 = *(float4*)&hs[rg * 256 + k];
        float4 a1 = *(float4*)&hs[(rg + 8) * 256 + k];
        acc0 += a0.x * b0 + a0.y * b1 + a0.z * b2 + a0.w * b3;
        acc1 += a1.x * b0 + a1.y * b1 + a1.z * b2 + a1.w * b3;
    }
    int gr0 = row0 + rg, gr1 = row0 + rg + 8;
    if (gr0 < n) g_h2[(size_t)gr0 * 32 + col] = acc0;
    if (gr1 < n) g_h2[(size_t)gr1 * 32 + col] = acc1;
    float s0 = acc0 * a2s[col], d0 = acc0 * a2d[col];
    float s1 = acc1 * a2s[col], d1 = acc1 * a2d[col];
    #pragma unroll
    for (int o = 16; o > 0; o >>= 1) {
        s0 += __shfl_xor_sync(0xffffffffu, s0, o);
        d0 += __shfl_xor_sync(0xffffffffu, d0, o);
        s1 += __shfl_xor_sync(0xffffffffu, s1, o);
        d1 += __shfl_xor_sync(0xffffffffu, d1, o);
    }
    if (col == 0) {
        if (gr0 < n) { g_asrc2[gr0] = s0; g_adst2[gr0] = d0; }
        if (gr1 < n) { g_asrc2[gr1] = s1; g_adst2[gr1] = d1; }
    }
}

// ---------------- layer-2 agg (single pass) + ELU + (@Wout + bout) -----------
__global__ __launch_bounds__(256) void k_agg2(const float* __restrict__ b2,
                                              const float* __restrict__ Wout,
                                              const float* __restrict__ bout,
                                              float* __restrict__ out, int n) {
    __shared__ float wos[32 * 16];
    __shared__ float bos[16];
    __shared__ float vsh[8][32];
    wos[threadIdx.x]       = Wout[threadIdx.x];
    wos[threadIdx.x + 256] = Wout[threadIdx.x + 256];
    if (threadIdx.x < 16)  bos[threadIdx.x] = bout[threadIdx.x];
    __syncthreads();

    int w = (blockIdx.x * blockDim.x + threadIdx.x) >> 5;
    int lane = threadIdx.x & 31;
    int wl = threadIdx.x >> 5;
    if (w >= n) return;

    float adv = g_adst2[w];
    int beg = g_off[w], end = g_off[w + 1];

    float ssum = 0.f, acc = 0.f;
    for (int base = beg; base < end; base += 32) {
        int cnt = end - base; if (cnt > 32) cnt = 32;
        int my = (lane < cnt) ? g_csr[base + lane] : 0;
        float mya = (lane < cnt) ? g_asrc2[my] : 0.f;
        for (int t = 0; t < cnt; t++) {
            int src  = __shfl_sync(0xffffffffu, my, t);
            float as = __shfl_sync(0xffffffffu, mya, t);
            float ev = __expf(leaky(as + adv));
            ssum += ev;
            acc  += ev * g_h2[(size_t)src * 32 + lane];
        }
    }
    {
        float evs = __expf(leaky(g_asrc2[w] + adv));
        ssum += evs;
        acc  += evs * g_h2[(size_t)w * 32 + lane];
    }
    acc = elu(acc / (ssum + 1e-16f) + b2[lane]);

    vsh[wl][lane] = acc;
    __syncwarp();
    if (lane < 16) {
        float o = bos[lane];
        #pragma unroll
        for (int c = 0; c < 32; c++) o += vsh[wl][c] * wos[c * 16 + lane];
        out[(size_t)w * FOUT + lane] = o;
    }
}

// ---------------- launch -----------------------------------------------------
extern "C" void kernel_launch(void* const* d_in, const int* in_sizes, int n_in,
                              void* d_out, int out_size) {
    const float* x        = (const float*)d_in[0];
    const int*   ei       = (const int*)d_in[1];
    const float* W1       = (const float*)d_in[2];
    const float* att_src1 = (const float*)d_in[3];
    const float* att_dst1 = (const float*)d_in[4];
    const float* b1       = (const float*)d_in[5];
    const float* W2       = (const float*)d_in[6];
    const float* att_src2 = (const float*)d_in[7];
    const float* att_dst2 = (const float*)d_in[8];
    const float* b2       = (const float*)d_in[9];
    const float* Wout     = (const float*)d_in[10];
    const float* bout     = (const float*)d_in[11];
    float*       out      = (float*)d_out;

    int n = in_sizes[0] / FIN;   // 50000
    int e = EFIX;                // 800000 (problem-fixed)

    // launch slot 4 = k_gemm1 (profiler lands there)
    k_detect <<<1, 1>>>(ei);
    k_zero   <<<(n + 255) / 256, 256>>>(n);
    k_count  <<<(e + 255) / 256, 256>>>(ei, e, n);
    dim3 g1((n + 127) / 128, 2);
    k_gemm1  <<<g1, 256>>>(x, W1, att_src1, att_dst1, n);
    k_scanA  <<<NBLK, 256>>>(n);
    k_scanB  <<<1, 256>>>(NBLK, n);
    k_scanC  <<<NBLK, 256>>>(n);
    k_scatter<<<(e + 255) / 256, 256>>>(ei, e, n);

    k_agg1 <<<(n + 7) / 8, 256>>>(b1, n);

    k_gemm2<<<(n + 15) / 16, 256>>>(W2, att_src2, att_dst2, n);
    k_agg2 <<<(n + 7) / 8, 256>>>(b2, Wout, bout, out, n);
}

// round 16
// speedup vs baseline: 1.6223x; 1.0089x over previous
#include <cuda_runtime.h>
#include <cuda_bf16.h>
#include <cuda_fp16.h>
#include <cstdint>
#include <math.h>

#define NMAX 50000
#define EFIX 800000
#define FIN  128
#define HC   256   // heads(8) * Hd(32)
#define H1   8
#define C2   32
#define FOUT 16
#define NBLK ((NMAX + 255) / 256)

// ---------------- scratch (static device globals; no allocation) -------------
__device__ __half2 g_h1h[NMAX * (HC / 2)];   // fp16 h1 (sole copy)
__device__ __half2 g_h1a[NMAX * (HC / 2)];   // fp16 h1 aggregated+ELU (sole copy)
__device__ __half  g_h2h[NMAX * C2];         // fp16 h2 (sole copy)
__device__ float g_asrc1[NMAX * H1];
__device__ float g_adst1[NMAX * H1];
__device__ float g_asrc2[NMAX];
__device__ float g_adst2[NMAX];
__device__ int   g_deg  [NMAX];
__device__ int   g_cur  [NMAX];
__device__ int   g_off  [NMAX + 1];
__device__ int   g_csr  [EFIX];
__device__ int   g_bsum [256];
__device__ int   g_bpre [256];
__device__ int   g_is64;

__device__ __forceinline__ float leaky(float x) { return x > 0.f ? x : 0.2f * x; }
__device__ __forceinline__ float elu(float x)   { return x > 0.f ? x : expm1f(x); }

// ---------------- tensor-core helpers ----------------------------------------
__device__ __forceinline__ unsigned smem_u32(const void* p) {
    unsigned addr;
    asm("{ .reg .u64 t; cvta.to.shared.u64 t, %1; cvt.u32.u64 %0, t; }"
        : "=r"(addr) : "l"(p));
    return addr;
}
__device__ __forceinline__ void ldsm_x4(unsigned& r0, unsigned& r1, unsigned& r2,
                                        unsigned& r3, unsigned addr) {
    asm volatile("ldmatrix.sync.aligned.m8n8.x4.shared.b16 {%0,%1,%2,%3}, [%4];"
                 : "=r"(r0), "=r"(r1), "=r"(r2), "=r"(r3) : "r"(addr));
}
__device__ __forceinline__ void ldsm_x4t(unsigned& r0, unsigned& r1, unsigned& r2,
                                         unsigned& r3, unsigned addr) {
    asm volatile("ldmatrix.sync.aligned.m8n8.x4.trans.shared.b16 {%0,%1,%2,%3}, [%4];"
                 : "=r"(r0), "=r"(r1), "=r"(r2), "=r"(r3) : "r"(addr));
}
__device__ __forceinline__ void mma_bf16(float* d, const unsigned* a,
                                         unsigned b0, unsigned b1) {
    asm volatile(
        "mma.sync.aligned.m16n8k16.row.col.f32.bf16.bf16.f32 "
        "{%0,%1,%2,%3}, {%4,%5,%6,%7}, {%8,%9}, {%0,%1,%2,%3};"
        : "+f"(d[0]), "+f"(d[1]), "+f"(d[2]), "+f"(d[3])
        : "r"(a[0]), "r"(a[1]), "r"(a[2]), "r"(a[3]), "r"(b0), "r"(b1));
}

// ---------------- dtype detection -------------------------------------------
__global__ void k_detect(const int* __restrict__ ei) {
    int z = 1;
    for (int i = 0; i < 64; i++)
        if (ei[2 * i + 1] != 0) { z = 0; break; }
    g_is64 = z;
}

// ---------------- CSR build --------------------------------------------------
__global__ void k_zero(int n) {
    int i = blockIdx.x * blockDim.x + threadIdx.x;
    if (i < n) { g_deg[i] = 0; g_cur[i] = 0; }
}

__global__ void k_count(const int* __restrict__ ei, int e, int n) {
    int i = blockIdx.x * blockDim.x + threadIdx.x;
    if (i < e) {
        int dst = g_is64 ? ei[2 * (e + i)] : ei[e + i];
        if ((unsigned)dst < (unsigned)n) atomicAdd(&g_deg[dst], 1);
    }
}

__global__ __launch_bounds__(256) void k_scanA(int n) {
    __shared__ int ws[8];
    int tid = threadIdx.x, lane = tid & 31, wid = tid >> 5;
    int idx = blockIdx.x * 256 + tid;
    int v = (idx < n) ? g_deg[idx] : 0;
    #pragma unroll
    for (int o = 16; o > 0; o >>= 1) v += __shfl_xor_sync(0xffffffffu, v, o);
    if (lane == 0) ws[wid] = v;
    __syncthreads();
    if (tid == 0) {
        int s = 0;
        #pragma unroll
        for (int i = 0; i < 8; i++) s += ws[i];
        g_bsum[blockIdx.x] = s;
    }
}

__global__ __launch_bounds__(256) void k_scanB(int nblk, int n) {
    __shared__ int wpre[8];
    int tid = threadIdx.x, lane = tid & 31, wid = tid >> 5;
    int v = (tid < nblk) ? g_bsum[tid] : 0;
    int inc = v;
    #pragma unroll
    for (int o = 1; o < 32; o <<= 1) {
        int t = __shfl_up_sync(0xffffffffu, inc, o);
        if (lane >= o) inc += t;
    }
    if (lane == 31) wpre[wid] = inc;
    __syncthreads();
    if (tid == 0) {
        int run = 0;
        #pragma unroll
        for (int i = 0; i < 8; i++) { int t = wpre[i]; wpre[i] = run; run += t; }
    }
    __syncthreads();
    int pre = inc - v + wpre[wid];
    if (tid < nblk) g_bpre[tid] = pre;
    if (tid == nblk - 1) g_off[n] = pre + v;
}

__global__ __launch_bounds__(256) void k_scanC(int n) {
    __shared__ int wpre[8];
    int tid = threadIdx.x, lane = tid & 31, wid = tid >> 5;
    int idx = blockIdx.x * 256 + tid;
    int v = (idx < n) ? g_deg[idx] : 0;
    int inc = v;
    #pragma unroll
    for (int o = 1; o < 32; o <<= 1) {
        int t = __shfl_up_sync(0xffffffffu, inc, o);
        if (lane >= o) inc += t;
    }
    if (lane == 31) wpre[wid] = inc;
    __syncthreads();
    if (tid == 0) {
        int run = 0;
        #pragma unroll
        for (int i = 0; i < 8; i++) { int t = wpre[i]; wpre[i] = run; run += t; }
    }
    __syncthreads();
    if (idx < n) g_off[idx] = g_bpre[blockIdx.x] + wpre[wid] + inc - v;
}

__global__ void k_scatter(const int* __restrict__ ei, int e, int n) {
    int i = blockIdx.x * blockDim.x + threadIdx.x;
    if (i < e) {
        int src, dst;
        if (g_is64) { src = ei[2 * i]; dst = ei[2 * (e + i)]; }
        else        { src = ei[i];     dst = ei[e + i]; }
        if ((unsigned)dst < (unsigned)n && (unsigned)src < (unsigned)n) {
            int pos = atomicAdd(&g_cur[dst], 1);
            g_csr[g_off[dst] + pos] = src;
        }
    }
}

// ---------------- GEMM1 (tensor cores) + fused attn1 -------------------------
#define XPAD 40
#define WPAD 136
__global__ __launch_bounds__(256) void k_gemm1(const float* __restrict__ x,
                                               const float* __restrict__ W,
                                               const float* __restrict__ att_s,
                                               const float* __restrict__ att_d, int n) {
    __shared__ __nv_bfloat16 xh[128][XPAD];
    __shared__ __nv_bfloat16 xl[128][XPAD];
    __shared__ __nv_bfloat16 wh[32][WPAD];
    __shared__ __nv_bfloat16 wl[32][WPAD];
    __shared__ float s_as[HC], s_ad[HC];

    int row0 = blockIdx.x * 128;
    int col0 = blockIdx.y * 128;
    int t = threadIdx.x;
    int lane = t & 31, warp = t >> 5;
    int wr = (warp & 3) * 32;
    int wc = (warp >> 2) * 64;

    if (t < HC) { s_as[t] = att_s[t]; s_ad[t] = att_d[t]; }

    float acc[2][8][4];
    #pragma unroll
    for (int i = 0; i < 2; i++)
        #pragma unroll
        for (int j = 0; j < 8; j++)
            #pragma unroll
            for (int q = 0; q < 4; q++) acc[i][j][q] = 0.f;

    int grp = lane >> 3;
    int rIn = (lane & 7) + ((grp & 1) << 3);
    int cIn = (grp >> 1) << 3;

    for (int kc = 0; kc < FIN; kc += 32) {
        #pragma unroll
        for (int i = 0; i < 4; i++) {
            int f = t + i * 256;
            int r = f >> 3, kq = f & 7;
            int gr = row0 + r;
            float4 v = make_float4(0.f, 0.f, 0.f, 0.f);
            if (gr < n) v = *(const float4*)&x[(size_t)gr * FIN + kc + kq * 4];
            float vv[4] = {v.x, v.y, v.z, v.w};
            #pragma unroll
            for (int j = 0; j < 4; j++) {
                __nv_bfloat16 hi = __float2bfloat16(vv[j]);
                xh[r][kq * 4 + j] = hi;
                xl[r][kq * 4 + j] = __float2bfloat16(vv[j] - __bfloat162float(hi));
            }
        }
        #pragma unroll
        for (int i = 0; i < 4; i++) {
            int f = t + i * 256;
            int k = f >> 5, c4 = f & 31;
            float4 v = *(const float4*)&W[(size_t)(kc + k) * HC + col0 + c4 * 4];
            float vv[4] = {v.x, v.y, v.z, v.w};
            #pragma unroll
            for (int j = 0; j < 4; j++) {
                __nv_bfloat16 hi = __float2bfloat16(vv[j]);
                wh[k][c4 * 4 + j] = hi;
                wl[k][c4 * 4 + j] = __float2bfloat16(vv[j] - __bfloat162float(hi));
            }
        }
        __syncthreads();

        #pragma unroll
        for (int k16 = 0; k16 < 32; k16 += 16) {
            unsigned Ah[2][4], Al[2][4];
            #pragma unroll
            for (int tt = 0; tt < 2; tt++) {
                int row = wr + tt * 16 + rIn;
                int col = k16 + cIn;
                ldsm_x4(Ah[tt][0], Ah[tt][1], Ah[tt][2], Ah[tt][3],
                        smem_u32(&xh[row][col]));
                ldsm_x4(Al[tt][0], Al[tt][1], Al[tt][2], Al[tt][3],
                        smem_u32(&xl[row][col]));
            }
            #pragma unroll
            for (int p = 0; p < 4; p++) {
                int row = k16 + rIn;
                int col = wc + p * 16 + cIn;
                unsigned Bh[4], Bl[4];
                ldsm_x4t(Bh[0], Bh[1], Bh[2], Bh[3], smem_u32(&wh[row][col]));
                ldsm_x4t(Bl[0], Bl[1], Bl[2], Bl[3], smem_u32(&wl[row][col]));
                #pragma unroll
                for (int tt = 0; tt < 2; tt++) {
                    #pragma unroll
                    for (int q = 0; q < 2; q++) {
                        float* d = acc[tt][p * 2 + q];
                        mma_bf16(d, Ah[tt], Bh[2 * q], Bh[2 * q + 1]);
                        mma_bf16(d, Ah[tt], Bl[2 * q], Bl[2 * q + 1]);
                        mma_bf16(d, Al[tt], Bh[2 * q], Bh[2 * q + 1]);
                    }
                }
            }
        }
        __syncthreads();
    }

    // epilogue: fp16 h1 store + fused attn1
    int hd0 = (col0 + wc) >> 5;
    #pragma unroll
    for (int tt = 0; tt < 2; tt++) {
        int gr0r = row0 + wr + tt * 16 + (lane >> 2);
        #pragma unroll
        for (int j = 0; j < 8; j++) {
            int gc = col0 + wc + j * 8 + (lane & 3) * 2;
            if (gr0r < n)
                g_h1h[(size_t)gr0r * (HC / 2) + (gc >> 1)] =
                    __floats2half2_rn(acc[tt][j][0], acc[tt][j][1]);
            if (gr0r + 8 < n)
                g_h1h[(size_t)(gr0r + 8) * (HC / 2) + (gc >> 1)] =
                    __floats2half2_rn(acc[tt][j][2], acc[tt][j][3]);
        }
        #pragma unroll
        for (int h = 0; h < 2; h++) {
            float psA = 0.f, pdA = 0.f, psB = 0.f, pdB = 0.f;
            #pragma unroll
            for (int jj = 0; jj < 4; jj++) {
                int j = h * 4 + jj;
                int c = col0 + wc + j * 8 + (lane & 3) * 2;
                float a0 = s_as[c], a1 = s_as[c + 1];
                float d0 = s_ad[c], d1 = s_ad[c + 1];
                psA += acc[tt][j][0] * a0 + acc[tt][j][1] * a1;
                pdA += acc[tt][j][0] * d0 + acc[tt][j][1] * d1;
                psB += acc[tt][j][2] * a0 + acc[tt][j][3] * a1;
                pdB += acc[tt][j][2] * d0 + acc[tt][j][3] * d1;
            }
            psA += __shfl_xor_sync(0xffffffffu, psA, 1);
            pdA += __shfl_xor_sync(0xffffffffu, pdA, 1);
            psB += __shfl_xor_sync(0xffffffffu, psB, 1);
            pdB += __shfl_xor_sync(0xffffffffu, pdB, 1);
            psA += __shfl_xor_sync(0xffffffffu, psA, 2);
            pdA += __shfl_xor_sync(0xffffffffu, pdA, 2);
            psB += __shfl_xor_sync(0xffffffffu, psB, 2);
            pdB += __shfl_xor_sync(0xffffffffu, pdB, 2);
            if ((lane & 3) == 0) {
                int gh = hd0 + h;
                if (gr0r < n) {
                    g_asrc1[gr0r * H1 + gh] = psA;
                    g_adst1[gr0r * H1 + gh] = pdA;
                }
                if (gr0r + 8 < n) {
                    g_asrc1[(gr0r + 8) * H1 + gh] = psB;
                    g_adst1[(gr0r + 8) * H1 + gh] = pdB;
                }
            }
        }
    }
}

// ---------------- layer-1 aggregation + ELU (fp16 gather, fp16 out) ----------
__global__ __launch_bounds__(256) void k_agg1(const float* __restrict__ b1, int n) {
    int w = (blockIdx.x * blockDim.x + threadIdx.x) >> 5;
    int lane = threadIdx.x & 31;
    if (w >= n) return;
    int beg = g_off[w], end = g_off[w + 1];

    int h1i = lane >> 3;
    int h2i = 4 + h1i;
    float adh1 = g_adst1[w * H1 + h1i];
    float adh2 = g_adst1[w * H1 + h2i];

    float ssum1 = 0.f, ssum2 = 0.f;
    float4 acc1 = make_float4(0.f, 0.f, 0.f, 0.f);
    float4 acc2 = make_float4(0.f, 0.f, 0.f, 0.f);

    for (int base = beg; base < end; base += 32) {
        int cnt = end - base; if (cnt > 32) cnt = 32;
        int my = (lane < cnt) ? g_csr[base + lane] : 0;
        for (int t = 0; t < cnt; t++) {
            int src = __shfl_sync(0xffffffffu, my, t);
            float ev1 = __expf(leaky(g_asrc1[src * H1 + h1i] + adh1));
            float ev2 = __expf(leaky(g_asrc1[src * H1 + h2i] + adh2));
            ssum1 += ev1; ssum2 += ev2;
            uint2 q1 = *(const uint2*)(g_h1h + (size_t)src * (HC / 2) + lane * 2);
            uint2 q2 = *(const uint2*)(g_h1h + (size_t)src * (HC / 2) + 64 + lane * 2);
            float2 a = __half22float2(*(__half2*)&q1.x);
            float2 b = __half22float2(*(__half2*)&q1.y);
            float2 c = __half22float2(*(__half2*)&q2.x);
            float2 d = __half22float2(*(__half2*)&q2.y);
            acc1.x += ev1 * a.x; acc1.y += ev1 * a.y; acc1.z += ev1 * b.x; acc1.w += ev1 * b.y;
            acc2.x += ev2 * c.x; acc2.y += ev2 * c.y; acc2.z += ev2 * d.x; acc2.w += ev2 * d.y;
        }
    }
    {
        float es1 = __expf(leaky(g_asrc1[w * H1 + h1i] + adh1));
        float es2 = __expf(leaky(g_asrc1[w * H1 + h2i] + adh2));
        ssum1 += es1; ssum2 += es2;
        uint2 q1 = *(const uint2*)(g_h1h + (size_t)w * (HC / 2) + lane * 2);
        uint2 q2 = *(const uint2*)(g_h1h + (size_t)w * (HC / 2) + 64 + lane * 2);
        float2 a = __half22float2(*(__half2*)&q1.x);
        float2 b = __half22float2(*(__half2*)&q1.y);
        float2 c = __half22float2(*(__half2*)&q2.x);
        float2 d = __half22float2(*(__half2*)&q2.y);
        acc1.x += es1 * a.x; acc1.y += es1 * a.y; acc1.z += es1 * b.x; acc1.w += es1 * b.y;
        acc2.x += es2 * c.x; acc2.y += es2 * c.y; acc2.z += es2 * d.x; acc2.w += es2 * d.y;
    }
    float iv1 = 1.f / (ssum1 + 1e-16f);
    float iv2 = 1.f / (ssum2 + 1e-16f);
    float4 bb1 = *(const float4*)&b1[lane * 4];
    float4 bb2 = *(const float4*)&b1[128 + lane * 4];
    float o0 = elu(acc1.x * iv1 + bb1.x), o1 = elu(acc1.y * iv1 + bb1.y);
    float o2 = elu(acc1.z * iv1 + bb1.z), o3 = elu(acc1.w * iv1 + bb1.w);
    float o4 = elu(acc2.x * iv2 + bb2.x), o5 = elu(acc2.y * iv2 + bb2.y);
    float o6 = elu(acc2.z * iv2 + bb2.z), o7 = elu(acc2.w * iv2 + bb2.w);
    // fp16 h1a (sole copy, consumed by gemm2)
    uint2 s1, s2;
    *(__half2*)&s1.x = __floats2half2_rn(o0, o1);
    *(__half2*)&s1.y = __floats2half2_rn(o2, o3);
    *(__half2*)&s2.x = __floats2half2_rn(o4, o5);
    *(__half2*)&s2.y = __floats2half2_rn(o6, o7);
    *(uint2*)(g_h1a + (size_t)w * (HC / 2) + lane * 2)      = s1;
    *(uint2*)(g_h1a + (size_t)w * (HC / 2) + 64 + lane * 2) = s2;
}

// ---------------- GEMM2 (+ fused attn2): h2 = h1a @ W2 -----------------------
__global__ __launch_bounds__(256) void k_gemm2(const float* __restrict__ W2,
                                               const float* __restrict__ att_s2,
                                               const float* __restrict__ att_d2, int n) {
    __shared__ float w2s[256 * 32];
    __shared__ float hs[16 * 256];
    __shared__ float a2s[32], a2d[32];
    int t = threadIdx.x;
    if (t < 32) { a2s[t] = att_s2[t]; a2d[t] = att_d2[t]; }
    #pragma unroll
    for (int i = 0; i < 8; i++)
        ((float4*)w2s)[t + i * 256] = ((const float4*)W2)[t + i * 256];
    int row0 = blockIdx.x * 16;
    // load fp16 h1a, convert to fp32 smem (16 rows x 128 half2 = 2048 half2)
    #pragma unroll
    for (int i = 0; i < 8; i++) {
        int idx = t + i * 256;            // half2 index: r = idx/128, c2 = idx%128
        int r = idx >> 7, c2 = idx & 127;
        int gr = row0 + r;
        __half2 v = __floats2half2_rn(0.f, 0.f);
        if (gr < n) v = g_h1a[(size_t)gr * (HC / 2) + c2];
        ((float2*)hs)[r * 128 + c2] = __half22float2(v);
    }
    __syncthreads();
    int col = t & 31, rg = t >> 5;
    float acc0 = 0.f, acc1 = 0.f;
    for (int k = 0; k < 256; k += 4) {
        float b0 = w2s[k * 32 + col];
        float b1 = w2s[(k + 1) * 32 + col];
        float b2 = w2s[(k + 2) * 32 + col];
        float b3 = w2s[(k + 3) * 32 + col];
        float4 a0 = *(float4*)&hs[rg * 256 + k];
        float4 a1 = *(float4*)&hs[(rg + 8) * 256 + k];
        acc0 += a0.x * b0 + a0.y * b1 + a0.z * b2 + a0.w * b3;
        acc1 += a1.x * b0 + a1.y * b1 + a1.z * b2 + a1.w * b3;
    }
    int gr0 = row0 + rg, gr1 = row0 + rg + 8;
    if (gr0 < n) g_h2h[(size_t)gr0 * 32 + col] = __float2half_rn(acc0);
    if (gr1 < n) g_h2h[(size_t)gr1 * 32 + col] = __float2half_rn(acc1);
    float s0 = acc0 * a2s[col], d0 = acc0 * a2d[col];
    float s1 = acc1 * a2s[col], d1 = acc1 * a2d[col];
    #pragma unroll
    for (int o = 16; o > 0; o >>= 1) {
        s0 += __shfl_xor_sync(0xffffffffu, s0, o);
        d0 += __shfl_xor_sync(0xffffffffu, d0, o);
        s1 += __shfl_xor_sync(0xffffffffu, s1, o);
        d1 += __shfl_xor_sync(0xffffffffu, d1, o);
    }
    if (col == 0) {
        if (gr0 < n) { g_asrc2[gr0] = s0; g_adst2[gr0] = d0; }
        if (gr1 < n) { g_asrc2[gr1] = s1; g_adst2[gr1] = d1; }
    }
}

// ---------------- layer-2 agg (fp16 gather) + ELU + (@Wout + bout) -----------
__global__ __launch_bounds__(256) void k_agg2(const float* __restrict__ b2,
                                              const float* __restrict__ Wout,
                                              const float* __restrict__ bout,
                                              float* __restrict__ out, int n) {
    __shared__ float wos[32 * 16];
    __shared__ float bos[16];
    __shared__ float vsh[8][32];
    wos[threadIdx.x]       = Wout[threadIdx.x];
    wos[threadIdx.x + 256] = Wout[threadIdx.x + 256];
    if (threadIdx.x < 16)  bos[threadIdx.x] = bout[threadIdx.x];
    __syncthreads();

    int w = (blockIdx.x * blockDim.x + threadIdx.x) >> 5;
    int lane = threadIdx.x & 31;
    int wl = threadIdx.x >> 5;
    if (w >= n) return;

    float adv = g_adst2[w];
    int beg = g_off[w], end = g_off[w + 1];

    float ssum = 0.f, acc = 0.f;
    for (int base = beg; base < end; base += 32) {
        int cnt = end - base; if (cnt > 32) cnt = 32;
        int my = (lane < cnt) ? g_csr[base + lane] : 0;
        float mya = (lane < cnt) ? g_asrc2[my] : 0.f;
        for (int t = 0; t < cnt; t++) {
            int src  = __shfl_sync(0xffffffffu, my, t);
            float as = __shfl_sync(0xffffffffu, mya, t);
            float ev = __expf(leaky(as + adv));
            ssum += ev;
            acc  += ev * __half2float(g_h2h[(size_t)src * 32 + lane]);
        }
    }
    {
        float evs = __expf(leaky(g_asrc2[w] + adv));
        ssum += evs;
        acc  += evs * __half2float(g_h2h[(size_t)w * 32 + lane]);
    }
    acc = elu(acc / (ssum + 1e-16f) + b2[lane]);

    vsh[wl][lane] = acc;
    __syncwarp();
    if (lane < 16) {
        float o = bos[lane];
        #pragma unroll
        for (int c = 0; c < 32; c++) o += vsh[wl][c] * wos[c * 16 + lane];
        out[(size_t)w * FOUT + lane] = o;
    }
}

// ---------------- launch -----------------------------------------------------
extern "C" void kernel_launch(void* const* d_in, const int* in_sizes, int n_in,
                              void* d_out, int out_size) {
    const float* x        = (const float*)d_in[0];
    const int*   ei       = (const int*)d_in[1];
    const float* W1       = (const float*)d_in[2];
    const float* att_src1 = (const float*)d_in[3];
    const float* att_dst1 = (const float*)d_in[4];
    const float* b1       = (const float*)d_in[5];
    const float* W2       = (const float*)d_in[6];
    const float* att_src2 = (const float*)d_in[7];
    const float* att_dst2 = (const float*)d_in[8];
    const float* b2       = (const float*)d_in[9];
    const float* Wout     = (const float*)d_in[10];
    const float* bout     = (const float*)d_in[11];
    float*       out      = (float*)d_out;

    int n = in_sizes[0] / FIN;   // 50000
    int e = EFIX;                // 800000 (problem-fixed)

    // launch slot 4 = k_gemm1 (profiler lands there)
    k_detect <<<1, 1>>>(ei);
    k_zero   <<<(n + 255) / 256, 256>>>(n);
    k_count  <<<(e + 255) / 256, 256>>>(ei, e, n);
    dim3 g1((n + 127) / 128, 2);
    k_gemm1  <<<g1, 256>>>(x, W1, att_src1, att_dst1, n);
    k_scanA  <<<NBLK, 256>>>(n);
    k_scanB  <<<1, 256>>>(NBLK, n);
    k_scanC  <<<NBLK, 256>>>(n);
    k_scatter<<<(e + 255) / 256, 256>>>(ei, e, n);

    k_agg1 <<<(n + 7) / 8, 256>>>(b1, n);

    k_gemm2<<<(n + 15) / 16, 256>>>(W2, att_src2, att_dst2, n);
    k_agg2 <<<(n + 7) / 8, 256>>>(b2, Wout, bout, out, n);
}

// round 17
// speedup vs baseline: 1.6950x; 1.0448x over previous
#include <cuda_runtime.h>
#include <cuda_bf16.h>
#include <cuda_fp16.h>
#include <cstdint>
#include <math.h>

#define NMAX 50000
#define EFIX 800000
#define FIN  128
#define HC   256   // heads(8) * Hd(32)
#define H1   8
#define C2   32
#define FOUT 16
#define NBLK ((NMAX + 255) / 256)

// ---------------- scratch (static device globals; no allocation) -------------
__device__ __half2 g_h1h[NMAX * (HC / 2)];   // fp16 h1 (sole copy)
__device__ __half2 g_h1a[NMAX * (HC / 2)];   // fp16 h1 aggregated+ELU (sole copy)
__device__ __half  g_h2h[NMAX * C2];         // fp16 h2 (sole copy)
__device__ float g_asrc1[NMAX * H1];
__device__ float g_adst1[NMAX * H1];
__device__ float g_asrc2[NMAX];
__device__ float g_adst2[NMAX];
__device__ int   g_deg  [NMAX];
__device__ int   g_cur  [NMAX];
__device__ int   g_off  [NMAX + 1];
__device__ int   g_csr  [EFIX];
__device__ int   g_bsum [256];
__device__ int   g_is64;

__device__ __forceinline__ float leaky(float x) { return x > 0.f ? x : 0.2f * x; }
__device__ __forceinline__ float elu(float x)   { return x > 0.f ? x : expm1f(x); }

// ---------------- tensor-core helpers ----------------------------------------
__device__ __forceinline__ unsigned smem_u32(const void* p) {
    unsigned addr;
    asm("{ .reg .u64 t; cvta.to.shared.u64 t, %1; cvt.u32.u64 %0, t; }"
        : "=r"(addr) : "l"(p));
    return addr;
}
__device__ __forceinline__ void ldsm_x4(unsigned& r0, unsigned& r1, unsigned& r2,
                                        unsigned& r3, unsigned addr) {
    asm volatile("ldmatrix.sync.aligned.m8n8.x4.shared.b16 {%0,%1,%2,%3}, [%4];"
                 : "=r"(r0), "=r"(r1), "=r"(r2), "=r"(r3) : "r"(addr));
}
__device__ __forceinline__ void ldsm_x4t(unsigned& r0, unsigned& r1, unsigned& r2,
                                         unsigned& r3, unsigned addr) {
    asm volatile("ldmatrix.sync.aligned.m8n8.x4.trans.shared.b16 {%0,%1,%2,%3}, [%4];"
                 : "=r"(r0), "=r"(r1), "=r"(r2), "=r"(r3) : "r"(addr));
}
__device__ __forceinline__ void mma_bf16(float* d, const unsigned* a,
                                         unsigned b0, unsigned b1) {
    asm volatile(
        "mma.sync.aligned.m16n8k16.row.col.f32.bf16.bf16.f32 "
        "{%0,%1,%2,%3}, {%4,%5,%6,%7}, {%8,%9}, {%0,%1,%2,%3};"
        : "+f"(d[0]), "+f"(d[1]), "+f"(d[2]), "+f"(d[3])
        : "r"(a[0]), "r"(a[1]), "r"(a[2]), "r"(a[3]), "r"(b0), "r"(b1));
}

// ---------------- zero + dtype detection (fused) -----------------------------
__global__ void k_zero(const int* __restrict__ ei, int n) {
    int i = blockIdx.x * blockDim.x + threadIdx.x;
    if (i < n) { g_deg[i] = 0; g_cur[i] = 0; }
    if (blockIdx.x == 0 && threadIdx.x == 0) {
        int z = 1;
        for (int k = 0; k < 64; k++)
            if (ei[2 * k + 1] != 0) { z = 0; break; }
        g_is64 = z;
    }
}

__global__ void k_count(const int* __restrict__ ei, int e, int n) {
    int i = blockIdx.x * blockDim.x + threadIdx.x;
    if (i < e) {
        int dst = g_is64 ? ei[2 * (e + i)] : ei[e + i];
        if ((unsigned)dst < (unsigned)n) atomicAdd(&g_deg[dst], 1);
    }
}

__global__ __launch_bounds__(256) void k_scanA(int n) {
    __shared__ int ws[8];
    int tid = threadIdx.x, lane = tid & 31, wid = tid >> 5;
    int idx = blockIdx.x * 256 + tid;
    int v = (idx < n) ? g_deg[idx] : 0;
    #pragma unroll
    for (int o = 16; o > 0; o >>= 1) v += __shfl_xor_sync(0xffffffffu, v, o);
    if (lane == 0) ws[wid] = v;
    __syncthreads();
    if (tid == 0) {
        int s = 0;
        #pragma unroll
        for (int i = 0; i < 8; i++) s += ws[i];
        g_bsum[blockIdx.x] = s;
    }
}

// scanC (merged with scanB): every block redundantly scans the block sums,
// takes its own prefix, then does the per-element exclusive scan.
__global__ __launch_bounds__(256) void k_scanC(int nblk, int n) {
    __shared__ int wpre[8], wpre2[8];
    __shared__ int bpre_sh;
    int tid = threadIdx.x, lane = tid & 31, wid = tid >> 5;

    // phase 1: exclusive scan of g_bsum[0..nblk)
    int v = (tid < nblk) ? g_bsum[tid] : 0;
    int inc = v;
    #pragma unroll
    for (int o = 1; o < 32; o <<= 1) {
        int t = __shfl_up_sync(0xffffffffu, inc, o);
        if (lane >= o) inc += t;
    }
    if (lane == 31) wpre[wid] = inc;
    __syncthreads();
    if (tid == 0) {
        int run = 0;
        #pragma unroll
        for (int i = 0; i < 8; i++) { int t = wpre[i]; wpre[i] = run; run += t; }
    }
    __syncthreads();
    int pre = inc - v + wpre[wid];
    if (tid == blockIdx.x) bpre_sh = pre;
    if (blockIdx.x == 0 && tid == nblk - 1) g_off[n] = pre + v;

    // phase 2: per-element exclusive scan of this block's degrees
    int idx = blockIdx.x * 256 + tid;
    int d = (idx < n) ? g_deg[idx] : 0;
    int incd = d;
    #pragma unroll
    for (int o = 1; o < 32; o <<= 1) {
        int t = __shfl_up_sync(0xffffffffu, incd, o);
        if (lane >= o) incd += t;
    }
    if (lane == 31) wpre2[wid] = incd;
    __syncthreads();
    if (tid == 0) {
        int run = 0;
        #pragma unroll
        for (int i = 0; i < 8; i++) { int t = wpre2[i]; wpre2[i] = run; run += t; }
    }
    __syncthreads();
    if (idx < n) g_off[idx] = bpre_sh + wpre2[wid] + incd - d;
}

__global__ void k_scatter(const int* __restrict__ ei, int e, int n) {
    int i = blockIdx.x * blockDim.x + threadIdx.x;
    if (i < e) {
        int src, dst;
        if (g_is64) { src = ei[2 * i]; dst = ei[2 * (e + i)]; }
        else        { src = ei[i];     dst = ei[e + i]; }
        if ((unsigned)dst < (unsigned)n && (unsigned)src < (unsigned)n) {
            int pos = atomicAdd(&g_cur[dst], 1);
            g_csr[g_off[dst] + pos] = src;
        }
    }
}

// ---------------- GEMM1 (tensor cores) + fused attn1 -------------------------
#define XPAD 40
#define WPAD 136
__global__ __launch_bounds__(256) void k_gemm1(const float* __restrict__ x,
                                               const float* __restrict__ W,
                                               const float* __restrict__ att_s,
                                               const float* __restrict__ att_d, int n) {
    __shared__ __nv_bfloat16 xh[128][XPAD];
    __shared__ __nv_bfloat16 xl[128][XPAD];
    __shared__ __nv_bfloat16 wh[32][WPAD];
    __shared__ __nv_bfloat16 wl[32][WPAD];
    __shared__ float s_as[HC], s_ad[HC];

    int row0 = blockIdx.x * 128;
    int col0 = blockIdx.y * 128;
    int t = threadIdx.x;
    int lane = t & 31, warp = t >> 5;
    int wr = (warp & 3) * 32;
    int wc = (warp >> 2) * 64;

    if (t < HC) { s_as[t] = att_s[t]; s_ad[t] = att_d[t]; }

    float acc[2][8][4];
    #pragma unroll
    for (int i = 0; i < 2; i++)
        #pragma unroll
        for (int j = 0; j < 8; j++)
            #pragma unroll
            for (int q = 0; q < 4; q++) acc[i][j][q] = 0.f;

    int grp = lane >> 3;
    int rIn = (lane & 7) + ((grp & 1) << 3);
    int cIn = (grp >> 1) << 3;

    for (int kc = 0; kc < FIN; kc += 32) {
        #pragma unroll
        for (int i = 0; i < 4; i++) {
            int f = t + i * 256;
            int r = f >> 3, kq = f & 7;
            int gr = row0 + r;
            float4 v = make_float4(0.f, 0.f, 0.f, 0.f);
            if (gr < n) v = *(const float4*)&x[(size_t)gr * FIN + kc + kq * 4];
            float vv[4] = {v.x, v.y, v.z, v.w};
            #pragma unroll
            for (int j = 0; j < 4; j++) {
                __nv_bfloat16 hi = __float2bfloat16(vv[j]);
                xh[r][kq * 4 + j] = hi;
                xl[r][kq * 4 + j] = __float2bfloat16(vv[j] - __bfloat162float(hi));
            }
        }
        #pragma unroll
        for (int i = 0; i < 4; i++) {
            int f = t + i * 256;
            int k = f >> 5, c4 = f & 31;
            float4 v = *(const float4*)&W[(size_t)(kc + k) * HC + col0 + c4 * 4];
            float vv[4] = {v.x, v.y, v.z, v.w};
            #pragma unroll
            for (int j = 0; j < 4; j++) {
                __nv_bfloat16 hi = __float2bfloat16(vv[j]);
                wh[k][c4 * 4 + j] = hi;
                wl[k][c4 * 4 + j] = __float2bfloat16(vv[j] - __bfloat162float(hi));
            }
        }
        __syncthreads();

        #pragma unroll
        for (int k16 = 0; k16 < 32; k16 += 16) {
            unsigned Ah[2][4], Al[2][4];
            #pragma unroll
            for (int tt = 0; tt < 2; tt++) {
                int row = wr + tt * 16 + rIn;
                int col = k16 + cIn;
                ldsm_x4(Ah[tt][0], Ah[tt][1], Ah[tt][2], Ah[tt][3],
                        smem_u32(&xh[row][col]));
                ldsm_x4(Al[tt][0], Al[tt][1], Al[tt][2], Al[tt][3],
                        smem_u32(&xl[row][col]));
            }
            #pragma unroll
            for (int p = 0; p < 4; p++) {
                int row = k16 + rIn;
                int col = wc + p * 16 + cIn;
                unsigned Bh[4], Bl[4];
                ldsm_x4t(Bh[0], Bh[1], Bh[2], Bh[3], smem_u32(&wh[row][col]));
                ldsm_x4t(Bl[0], Bl[1], Bl[2], Bl[3], smem_u32(&wl[row][col]));
                #pragma unroll
                for (int tt = 0; tt < 2; tt++) {
                    #pragma unroll
                    for (int q = 0; q < 2; q++) {
                        float* d = acc[tt][p * 2 + q];
                        mma_bf16(d, Ah[tt], Bh[2 * q], Bh[2 * q + 1]);
                        mma_bf16(d, Ah[tt], Bl[2 * q], Bl[2 * q + 1]);
                        mma_bf16(d, Al[tt], Bh[2 * q], Bh[2 * q + 1]);
                    }
                }
            }
        }
        __syncthreads();
    }

    // epilogue: fp16 h1 store + fused attn1
    int hd0 = (col0 + wc) >> 5;
    #pragma unroll
    for (int tt = 0; tt < 2; tt++) {
        int gr0r = row0 + wr + tt * 16 + (lane >> 2);
        #pragma unroll
        for (int j = 0; j < 8; j++) {
            int gc = col0 + wc + j * 8 + (lane & 3) * 2;
            if (gr0r < n)
                g_h1h[(size_t)gr0r * (HC / 2) + (gc >> 1)] =
                    __floats2half2_rn(acc[tt][j][0], acc[tt][j][1]);
            if (gr0r + 8 < n)
                g_h1h[(size_t)(gr0r + 8) * (HC / 2) + (gc >> 1)] =
                    __floats2half2_rn(acc[tt][j][2], acc[tt][j][3]);
        }
        #pragma unroll
        for (int h = 0; h < 2; h++) {
            float psA = 0.f, pdA = 0.f, psB = 0.f, pdB = 0.f;
            #pragma unroll
            for (int jj = 0; jj < 4; jj++) {
                int j = h * 4 + jj;
                int c = col0 + wc + j * 8 + (lane & 3) * 2;
                float a0 = s_as[c], a1 = s_as[c + 1];
                float d0 = s_ad[c], d1 = s_ad[c + 1];
                psA += acc[tt][j][0] * a0 + acc[tt][j][1] * a1;
                pdA += acc[tt][j][0] * d0 + acc[tt][j][1] * d1;
                psB += acc[tt][j][2] * a0 + acc[tt][j][3] * a1;
                pdB += acc[tt][j][2] * d0 + acc[tt][j][3] * d1;
            }
            psA += __shfl_xor_sync(0xffffffffu, psA, 1);
            pdA += __shfl_xor_sync(0xffffffffu, pdA, 1);
            psB += __shfl_xor_sync(0xffffffffu, psB, 1);
            pdB += __shfl_xor_sync(0xffffffffu, pdB, 1);
            psA += __shfl_xor_sync(0xffffffffu, psA, 2);
            pdA += __shfl_xor_sync(0xffffffffu, pdA, 2);
            psB += __shfl_xor_sync(0xffffffffu, psB, 2);
            pdB += __shfl_xor_sync(0xffffffffu, pdB, 2);
            if ((lane & 3) == 0) {
                int gh = hd0 + h;
                if (gr0r < n) {
                    g_asrc1[gr0r * H1 + gh] = psA;
                    g_adst1[gr0r * H1 + gh] = pdA;
                }
                if (gr0r + 8 < n) {
                    g_asrc1[(gr0r + 8) * H1 + gh] = psB;
                    g_adst1[(gr0r + 8) * H1 + gh] = pdB;
                }
            }
        }
    }
}

// ---------------- layer-1 aggregation + ELU (fp16 gather, broadcast loop) ----
__global__ __launch_bounds__(256) void k_agg1(const float* __restrict__ b1, int n) {
    int w = (blockIdx.x * blockDim.x + threadIdx.x) >> 5;
    int lane = threadIdx.x & 31;
    if (w >= n) return;
    int beg = g_off[w], end = g_off[w + 1];

    int h1i = lane >> 3;
    int h2i = 4 + h1i;
    float adh1 = g_adst1[w * H1 + h1i];
    float adh2 = g_adst1[w * H1 + h2i];

    float ssum1 = 0.f, ssum2 = 0.f;
    float4 acc1 = make_float4(0.f, 0.f, 0.f, 0.f);
    float4 acc2 = make_float4(0.f, 0.f, 0.f, 0.f);

    // all lanes read the same csr entry (1-wavefront broadcast, L1-cached)
    #pragma unroll 4
    for (int i = beg; i < end; i++) {
        int src = g_csr[i];
        float ev1 = __expf(leaky(g_asrc1[src * H1 + h1i] + adh1));
        float ev2 = __expf(leaky(g_asrc1[src * H1 + h2i] + adh2));
        ssum1 += ev1; ssum2 += ev2;
        uint2 q1 = *(const uint2*)(g_h1h + (size_t)src * (HC / 2) + lane * 2);
        uint2 q2 = *(const uint2*)(g_h1h + (size_t)src * (HC / 2) + 64 + lane * 2);
        float2 a = __half22float2(*(__half2*)&q1.x);
        float2 b = __half22float2(*(__half2*)&q1.y);
        float2 c = __half22float2(*(__half2*)&q2.x);
        float2 d = __half22float2(*(__half2*)&q2.y);
        acc1.x += ev1 * a.x; acc1.y += ev1 * a.y; acc1.z += ev1 * b.x; acc1.w += ev1 * b.y;
        acc2.x += ev2 * c.x; acc2.y += ev2 * c.y; acc2.z += ev2 * d.x; acc2.w += ev2 * d.y;
    }
    {
        float es1 = __expf(leaky(g_asrc1[w * H1 + h1i] + adh1));
        float es2 = __expf(leaky(g_asrc1[w * H1 + h2i] + adh2));
        ssum1 += es1; ssum2 += es2;
        uint2 q1 = *(const uint2*)(g_h1h + (size_t)w * (HC / 2) + lane * 2);
        uint2 q2 = *(const uint2*)(g_h1h + (size_t)w * (HC / 2) + 64 + lane * 2);
        float2 a = __half22float2(*(__half2*)&q1.x);
        float2 b = __half22float2(*(__half2*)&q1.y);
        float2 c = __half22float2(*(__half2*)&q2.x);
        float2 d = __half22float2(*(__half2*)&q2.y);
        acc1.x += es1 * a.x; acc1.y += es1 * a.y; acc1.z += es1 * b.x; acc1.w += es1 * b.y;
        acc2.x += es2 * c.x; acc2.y += es2 * c.y; acc2.z += es2 * d.x; acc2.w += es2 * d.y;
    }
    float iv1 = 1.f / (ssum1 + 1e-16f);
    float iv2 = 1.f / (ssum2 + 1e-16f);
    float4 bb1 = *(const float4*)&b1[lane * 4];
    float4 bb2 = *(const float4*)&b1[128 + lane * 4];
    float o0 = elu(acc1.x * iv1 + bb1.x), o1 = elu(acc1.y * iv1 + bb1.y);
    float o2 = elu(acc1.z * iv1 + bb1.z), o3 = elu(acc1.w * iv1 + bb1.w);
    float o4 = elu(acc2.x * iv2 + bb2.x), o5 = elu(acc2.y * iv2 + bb2.y);
    float o6 = elu(acc2.z * iv2 + bb2.z), o7 = elu(acc2.w * iv2 + bb2.w);
    uint2 s1, s2;
    *(__half2*)&s1.x = __floats2half2_rn(o0, o1);
    *(__half2*)&s1.y = __floats2half2_rn(o2, o3);
    *(__half2*)&s2.x = __floats2half2_rn(o4, o5);
    *(__half2*)&s2.y = __floats2half2_rn(o6, o7);
    *(uint2*)(g_h1a + (size_t)w * (HC / 2) + lane * 2)      = s1;
    *(uint2*)(g_h1a + (size_t)w * (HC / 2) + 64 + lane * 2) = s2;
}

// ---------------- GEMM2 (+ fused attn2): h2 = h1a @ W2 -----------------------
__global__ __launch_bounds__(256) void k_gemm2(const float* __restrict__ W2,
                                               const float* __restrict__ att_s2,
                                               const float* __restrict__ att_d2, int n) {
    __shared__ float w2s[256 * 32];
    __shared__ float hs[16 * 256];
    __shared__ float a2s[32], a2d[32];
    int t = threadIdx.x;
    if (t < 32) { a2s[t] = att_s2[t]; a2d[t] = att_d2[t]; }
    #pragma unroll
    for (int i = 0; i < 8; i++)
        ((float4*)w2s)[t + i * 256] = ((const float4*)W2)[t + i * 256];
    int row0 = blockIdx.x * 16;
    #pragma unroll
    for (int i = 0; i < 8; i++) {
        int idx = t + i * 256;
        int r = idx >> 7, c2 = idx & 127;
        int gr = row0 + r;
        __half2 v = __floats2half2_rn(0.f, 0.f);
        if (gr < n) v = g_h1a[(size_t)gr * (HC / 2) + c2];
        ((float2*)hs)[r * 128 + c2] = __half22float2(v);
    }
    __syncthreads();
    int col = t & 31, rg = t >> 5;
    float acc0 = 0.f, acc1 = 0.f;
    for (int k = 0; k < 256; k += 4) {
        float b0 = w2s[k * 32 + col];
        float b1 = w2s[(k + 1) * 32 + col];
        float b2 = w2s[(k + 2) * 32 + col];
        float b3 = w2s[(k + 3) * 32 + col];
        float4 a0 = *(float4*)&hs[rg * 256 + k];
        float4 a1 = *(float4*)&hs[(rg + 8) * 256 + k];
        acc0 += a0.x * b0 + a0.y * b1 + a0.z * b2 + a0.w * b3;
        acc1 += a1.x * b0 + a1.y * b1 + a1.z * b2 + a1.w * b3;
    }
    int gr0 = row0 + rg, gr1 = row0 + rg + 8;
    if (gr0 < n) g_h2h[(size_t)gr0 * 32 + col] = __float2half_rn(acc0);
    if (gr1 < n) g_h2h[(size_t)gr1 * 32 + col] = __float2half_rn(acc1);
    float s0 = acc0 * a2s[col], d0 = acc0 * a2d[col];
    float s1 = acc1 * a2s[col], d1 = acc1 * a2d[col];
    #pragma unroll
    for (int o = 16; o > 0; o >>= 1) {
        s0 += __shfl_xor_sync(0xffffffffu, s0, o);
        d0 += __shfl_xor_sync(0xffffffffu, d0, o);
        s1 += __shfl_xor_sync(0xffffffffu, s1, o);
        d1 += __shfl_xor_sync(0xffffffffu, d1, o);
    }
    if (col == 0) {
        if (gr0 < n) { g_asrc2[gr0] = s0; g_adst2[gr0] = d0; }
        if (gr1 < n) { g_asrc2[gr1] = s1; g_adst2[gr1] = d1; }
    }
}

// ---------------- layer-2 agg (fp16 gather, broadcast loop) + proj -----------
__global__ __launch_bounds__(256) void k_agg2(const float* __restrict__ b2,
                                              const float* __restrict__ Wout,
                                              const float* __restrict__ bout,
                                              float* __restrict__ out, int n) {
    __shared__ float wos[32 * 16];
    __shared__ float bos[16];
    __shared__ float vsh[8][32];
    wos[threadIdx.x]       = Wout[threadIdx.x];
    wos[threadIdx.x + 256] = Wout[threadIdx.x + 256];
    if (threadIdx.x < 16)  bos[threadIdx.x] = bout[threadIdx.x];
    __syncthreads();

    int w = (blockIdx.x * blockDim.x + threadIdx.x) >> 5;
    int lane = threadIdx.x & 31;
    int wl = threadIdx.x >> 5;
    if (w >= n) return;

    float adv = g_adst2[w];
    int beg = g_off[w], end = g_off[w + 1];

    float ssum = 0.f, acc = 0.f;
    #pragma unroll 4
    for (int i = beg; i < end; i++) {
        int src = g_csr[i];
        float ev = __expf(leaky(g_asrc2[src] + adv));
        ssum += ev;
        acc  += ev * __half2float(g_h2h[(size_t)src * 32 + lane]);
    }
    {
        float evs = __expf(leaky(g_asrc2[w] + adv));
        ssum += evs;
        acc  += evs * __half2float(g_h2h[(size_t)w * 32 + lane]);
    }
    acc = elu(acc / (ssum + 1e-16f) + b2[lane]);

    vsh[wl][lane] = acc;
    __syncwarp();
    if (lane < 16) {
        float o = bos[lane];
        #pragma unroll
        for (int c = 0; c < 32; c++) o += vsh[wl][c] * wos[c * 16 + lane];
        out[(size_t)w * FOUT + lane] = o;
    }
}

// ---------------- launch -----------------------------------------------------
extern "C" void kernel_launch(void* const* d_in, const int* in_sizes, int n_in,
                              void* d_out, int out_size) {
    const float* x        = (const float*)d_in[0];
    const int*   ei       = (const int*)d_in[1];
    const float* W1       = (const float*)d_in[2];
    const float* att_src1 = (const float*)d_in[3];
    const float* att_dst1 = (const float*)d_in[4];
    const float* b1       = (const float*)d_in[5];
    const float* W2       = (const float*)d_in[6];
    const float* att_src2 = (const float*)d_in[7];
    const float* att_dst2 = (const float*)d_in[8];
    const float* b2       = (const float*)d_in[9];
    const float* Wout     = (const float*)d_in[10];
    const float* bout     = (const float*)d_in[11];
    float*       out      = (float*)d_out;

    int n = in_sizes[0] / FIN;   // 50000
    int e = EFIX;                // 800000 (problem-fixed)

    // slot 4 = k_gemm1 (profiler lands there)
    k_zero   <<<(n + 255) / 256, 256>>>(ei, n);
    k_count  <<<(e + 255) / 256, 256>>>(ei, e, n);
    k_scanA  <<<NBLK, 256>>>(n);
    dim3 g1((n + 127) / 128, 2);
    k_gemm1  <<<g1, 256>>>(x, W1, att_src1, att_dst1, n);
    k_scanC  <<<NBLK, 256>>>(NBLK, n);
    k_scatter<<<(e + 255) / 256, 256>>>(ei, e, n);

    k_agg1 <<<(n + 7) / 8, 256>>>(b1, n);

    k_gemm2<<<(n + 15) / 16, 256>>>(W2, att_src2, att_dst2, n);
    k_agg2 <<<(n + 7) / 8, 256>>>(b2, Wout, bout, out, n);
}